// round 1
// baseline (speedup 1.0000x reference)
#include <cuda_runtime.h>
#include <math.h>

#define NB     128
#define NCELLS 81
#define NNODE  (NB*NCELLS)     // 10368
#define HD     96
#define TSTEPS 16

// ------------------------- device scratch (no allocs) -------------------------
__device__ float g_x[NNODE*HD];
__device__ float g_gx[NNODE*4*HD];
__device__ float g_S1[NNODE*6*HD];      // per-row: [a_src(96) | a_dst(96) | hW(384)]
__device__ float g_m[NNODE*HD];
__device__ float g_gm[NNODE*4*HD];
__device__ float g_h[NNODE*HD];
__device__ float g_c[NNODE*HD];
__device__ float g_WTmsg[3*HD*HD];      // transposed msg_W layers
__device__ float g_WTin[3*HD*HD];       // transposed in_W layers
__device__ float g_WTin0[48*HD];        // transposed in_W0
__device__ float g_Wpack[6*HD*HD];      // [576,96] = [W0a; W0b; W_hh]
__device__ float g_logits[(size_t)TSTEPS*NNODE*10];
__device__ double g_loss;

// ------------------------- weight packing / transpose -------------------------
__global__ void pack_kernel(const float* __restrict__ msg_W,
                            const float* __restrict__ in_W,
                            const float* __restrict__ in_W0,
                            const float* __restrict__ msg_W0,
                            const float* __restrict__ W_hh)
{
    int i = blockIdx.x*blockDim.x + threadIdx.x;
    int stride = gridDim.x*blockDim.x;
    for (int idx = i; idx < 3*HD*HD; idx += stride) {
        int l = idx / (HD*HD), r = idx % (HD*HD);
        int k = r / HD, j = r % HD;
        g_WTmsg[idx] = msg_W[l*HD*HD + j*HD + k];
        g_WTin[idx]  = in_W [l*HD*HD + j*HD + k];
    }
    for (int idx = i; idx < 48*HD; idx += stride) {
        int k = idx / HD, j = idx % HD;
        g_WTin0[idx] = in_W0[j*48 + k];
    }
    for (int idx = i; idx < 576*HD; idx += stride) {
        int o = idx / HD, k = idx % HD;
        float v;
        if (o < 96)       v = msg_W0[o*192 + k];            // W0a (src half)
        else if (o < 192) v = msg_W0[(o-96)*192 + 96 + k];  // W0b (dst half)
        else              v = W_hh[(o-192)*HD + k];
        g_Wpack[idx] = v;
    }
    if (i == 0) g_loss = 0.0;
}

// ------------------------- generic sgemm: C = A @ W^T -------------------------
// A [M,96] row-major, W rows at stride ldw with column offset woff, C [M,Nc].
// Requires M%64==0, Nc%64==0.
__global__ void __launch_bounds__(256) sgemm_awt(const float* __restrict__ A,
                                                 const float* __restrict__ W,
                                                 float* __restrict__ C,
                                                 int Nc, int ldw, int woff)
{
    __shared__ float As[16][65];
    __shared__ float Ws[16][65];
    int bm = blockIdx.y * 64, bn = blockIdx.x * 64;
    int tid = threadIdx.x;
    int tx = tid & 15, ty = tid >> 4;
    int lr = tid >> 2, lk = (tid & 3) << 2;
    float acc[4][4];
    #pragma unroll
    for (int i = 0; i < 4; i++)
        #pragma unroll
        for (int j = 0; j < 4; j++) acc[i][j] = 0.f;

    for (int k0 = 0; k0 < 96; k0 += 16) {
        float4 a = *(const float4*)(A + (size_t)(bm+lr)*96 + k0 + lk);
        As[lk+0][lr]=a.x; As[lk+1][lr]=a.y; As[lk+2][lr]=a.z; As[lk+3][lr]=a.w;
        float4 w = *(const float4*)(W + (size_t)(bn+lr)*ldw + woff + k0 + lk);
        Ws[lk+0][lr]=w.x; Ws[lk+1][lr]=w.y; Ws[lk+2][lr]=w.z; Ws[lk+3][lr]=w.w;
        __syncthreads();
        #pragma unroll
        for (int k = 0; k < 16; k++) {
            float av[4], wv[4];
            #pragma unroll
            for (int i = 0; i < 4; i++) av[i] = As[k][ty*4+i];
            #pragma unroll
            for (int j = 0; j < 4; j++) wv[j] = Ws[k][tx*4+j];
            #pragma unroll
            for (int i = 0; i < 4; i++)
                #pragma unroll
                for (int j = 0; j < 4; j++)
                    acc[i][j] = fmaf(av[i], wv[j], acc[i][j]);
        }
        __syncthreads();
    }
    #pragma unroll
    for (int i = 0; i < 4; i++) {
        float4 o = make_float4(acc[i][0], acc[i][1], acc[i][2], acc[i][3]);
        *(float4*)(C + (size_t)(bm + ty*4 + i)*Nc + bn + tx*4) = o;
    }
}

// ------------------------- helpers -------------------------
__device__ __forceinline__ float dot96(const float* __restrict__ WTcol,
                                       const float* __restrict__ vin)
{
    float s = 0.f;
    #pragma unroll 8
    for (int k4 = 0; k4 < 24; k4++) {
        float4 a = ((const float4*)vin)[k4];
        s = fmaf(WTcol[(4*k4+0)*96], a.x, s);
        s = fmaf(WTcol[(4*k4+1)*96], a.y, s);
        s = fmaf(WTcol[(4*k4+2)*96], a.z, s);
        s = fmaf(WTcol[(4*k4+3)*96], a.w, s);
    }
    return s;
}

// 4-edge fused 96->96 layer: s.{x,y,z,w} accumulate for edges 0..3
__device__ __forceinline__ void layer4(const float* __restrict__ WTcol,
                                       const float* __restrict__ vin, float4& s)
{
    #pragma unroll 8
    for (int k4 = 0; k4 < 24; k4++) {
        float w0 = WTcol[(4*k4+0)*96];
        float w1 = WTcol[(4*k4+1)*96];
        float w2 = WTcol[(4*k4+2)*96];
        float w3 = WTcol[(4*k4+3)*96];
        float4 a0 = ((const float4*)(vin      ))[k4];
        float4 a1 = ((const float4*)(vin +  96))[k4];
        float4 a2 = ((const float4*)(vin + 192))[k4];
        float4 a3 = ((const float4*)(vin + 288))[k4];
        s.x = fmaf(w3,a0.w, fmaf(w2,a0.z, fmaf(w1,a0.y, fmaf(w0,a0.x, s.x))));
        s.y = fmaf(w3,a1.w, fmaf(w2,a1.z, fmaf(w1,a1.y, fmaf(w0,a1.x, s.y))));
        s.z = fmaf(w3,a2.w, fmaf(w2,a2.z, fmaf(w1,a2.y, fmaf(w0,a2.x, s.z))));
        s.w = fmaf(w3,a3.w, fmaf(w2,a3.z, fmaf(w1,a3.y, fmaf(w0,a3.x, s.w))));
    }
}

// ------------------------- input embedding + MLP -------------------------
// dyn smem: sW0[48*96] | sWT[3*9216] | per-slot v0[48],vA[96],vB[96]
__global__ void __launch_bounds__(768) input_kernel(const int* __restrict__ q,
    const int* __restrict__ rw, const int* __restrict__ cl,
    const float* __restrict__ demb, const float* __restrict__ remb,
    const float* __restrict__ cemb, const float* __restrict__ inb)
{
    extern __shared__ float sm[];
    float* sW0 = sm;
    float* sWT = sm + 48*96;
    float* svb = sWT + 3*9216;
    for (int i = threadIdx.x; i < 48*96;  i += 768) sW0[i] = g_WTin0[i];
    for (int i = threadIdx.x; i < 3*9216; i += 768) sWT[i] = g_WTin[i];
    __syncthreads();

    int slot = threadIdx.x / 96, j = threadIdx.x % 96;
    float* v0 = svb + slot*240;
    float* vA = v0 + 48;
    float* vB = vA + 96;
    int sg = blockIdx.x*8 + slot;
    int stride = gridDim.x*8;
    int iters = (NNODE + stride - 1) / stride;
    float b0 = inb[j], b1 = inb[96+j], b2 = inb[192+j], b3 = inb[288+j];

    for (int it = 0; it < iters; it++) {
        int node = sg + it*stride;
        bool act = node < NNODE;
        int n = act ? node : NNODE-1;
        if (j < 16)      v0[j] = demb[q[n]*16 + j];
        else if (j < 32) v0[j] = remb[rw[n]*16 + (j-16)];
        else if (j < 48) v0[j] = cemb[cl[n]*16 + (j-32)];
        __syncthreads();
        float s = b0;
        #pragma unroll
        for (int k4 = 0; k4 < 12; k4++) {
            float4 a = ((const float4*)v0)[k4];
            s = fmaf(sW0[(4*k4+0)*96+j], a.x, s);
            s = fmaf(sW0[(4*k4+1)*96+j], a.y, s);
            s = fmaf(sW0[(4*k4+2)*96+j], a.z, s);
            s = fmaf(sW0[(4*k4+3)*96+j], a.w, s);
        }
        vA[j] = fmaxf(s, 0.f);
        __syncthreads();
        float t1 = b1 + dot96(sWT + j, vA);
        vB[j] = fmaxf(t1, 0.f);
        __syncthreads();
        float t2 = b2 + dot96(sWT + 9216 + j, vB);
        vA[j] = fmaxf(t2, 0.f);
        __syncthreads();
        float t3 = b3 + dot96(sWT + 2*9216 + j, vA);
        if (act) {
            g_x[(size_t)node*96 + j] = t3;
            g_h[(size_t)node*96 + j] = t3;   // h0 = x
            g_c[(size_t)node*96 + j] = 0.f;  // c0 = 0
        }
        __syncthreads();
    }
}

// ------------------------- edge message MLP + aggregation -------------------------
// dyn smem: sWT[3*9216] | per-slot vb[2][4][96] | nbr[81*20]
__global__ void __launch_bounds__(768) msg_kernel(const float* __restrict__ msgb)
{
    extern __shared__ float sm[];
    float* sWT = sm;
    float* svb = sWT + 3*9216;
    int*  snbr = (int*)(svb + 8*768);
    for (int i = threadIdx.x; i < 3*9216; i += 768) sWT[i] = g_WTmsg[i];
    if (threadIdx.x < 81) {
        int u = threadIdx.x;
        int ru = u/9, cu = u%9, bu = (ru/3)*3 + cu/3;
        int cnt = 0;
        for (int v = 0; v < 81; v++) {
            if (v == u) continue;
            int rv = v/9, cv = v%9, bv = (rv/3)*3 + cv/3;
            if (rv == ru || cv == cu || bv == bu) snbr[u*20 + cnt++] = v;
        }
    }
    __syncthreads();

    int slot = threadIdx.x / 96, j = threadIdx.x % 96;
    float* vb0 = svb + slot*768;
    float* vb1 = vb0 + 384;
    int sg = blockIdx.x*8 + slot;
    int stride = gridDim.x*8;
    int iters = (NNODE + stride - 1) / stride;
    float b0 = msgb[j], b1 = msgb[96+j], b2 = msgb[192+j], b3 = msgb[288+j];

    for (int it = 0; it < iters; it++) {
        int node = sg + it*stride;
        bool act = node < NNODE;
        int n = act ? node : NNODE-1;
        int cell = n % 81;
        int base = n - cell;
        float ad = g_S1[(size_t)n*576 + 96 + j] + b0;   // a_dst + b[0]
        float acc = 0.f;
        #pragma unroll 1
        for (int g = 0; g < 5; g++) {
            #pragma unroll
            for (int e = 0; e < 4; e++) {
                int u = base + snbr[cell*20 + g*4 + e];
                vb0[e*96 + j] = fmaxf(g_S1[(size_t)u*576 + j] + ad, 0.f);
            }
            __syncthreads();
            float4 s = make_float4(b1,b1,b1,b1);
            layer4(sWT + j, vb0, s);
            vb1[      j] = fmaxf(s.x, 0.f);
            vb1[ 96 + j] = fmaxf(s.y, 0.f);
            vb1[192 + j] = fmaxf(s.z, 0.f);
            vb1[288 + j] = fmaxf(s.w, 0.f);
            __syncthreads();
            s = make_float4(b2,b2,b2,b2);
            layer4(sWT + 9216 + j, vb1, s);
            vb0[      j] = fmaxf(s.x, 0.f);
            vb0[ 96 + j] = fmaxf(s.y, 0.f);
            vb0[192 + j] = fmaxf(s.z, 0.f);
            vb0[288 + j] = fmaxf(s.w, 0.f);
            __syncthreads();
            s = make_float4(b3,b3,b3,b3);
            layer4(sWT + 2*9216 + j, vb0, s);
            acc += s.x + s.y + s.z + s.w;
            __syncthreads();
        }
        if (act) g_m[(size_t)node*96 + j] = acc;
    }
}

// ------------------------- LSTM pointwise + per-step logits -------------------------
__global__ void __launch_bounds__(96) lstm_kernel(const float* __restrict__ outW,
                                                  const float* __restrict__ outb, int t)
{
    int n = blockIdx.x, j = threadIdx.x;
    __shared__ float sh[HD];
    size_t b4 = (size_t)n*384 + j;
    float gi = g_gx[b4      ] + g_gm[b4      ];
    float gf = g_gx[b4 +  96] + g_gm[b4 +  96];
    float gg = g_gx[b4 + 192] + g_gm[b4 + 192];
    float go = g_gx[b4 + 288] + g_gm[b4 + 288];
    if (t > 0) {
        const float* hw = g_S1 + (size_t)n*576 + 192 + j;
        gi += hw[0]; gf += hw[96]; gg += hw[192]; go += hw[288];
    }
    float si = 1.f/(1.f + expf(-gi));
    float sf = 1.f/(1.f + expf(-gf));
    float so = 1.f/(1.f + expf(-go));
    float cn = sf * g_c[(size_t)n*96 + j] + si * tanhf(gg);
    float hn = so * tanhf(cn);
    g_c[(size_t)n*96 + j] = cn;
    g_h[(size_t)n*96 + j] = hn;
    sh[j] = hn;
    __syncthreads();
    if (j < 10) {
        float s = outb[j];
        const float* w = outW + j*96;
        #pragma unroll 8
        for (int k = 0; k < 96; k++) s = fmaf(sh[k], w[k], s);
        g_logits[((size_t)t*NNODE + n)*10 + j] = s;
    }
}

// ------------------------- preds / loss / lf -------------------------
__global__ void finalize_kernel(const int* __restrict__ labels,
                                float* __restrict__ out, int out_size)
{
    int idx = blockIdx.x*blockDim.x + threadIdx.x;
    if (idx >= TSTEPS*NNODE) return;
    const float* l = g_logits + (size_t)idx*10;
    float mx = l[0]; int am = 0;
    #pragma unroll
    for (int d = 1; d < 10; d++) if (l[d] > mx) { mx = l[d]; am = d; }
    float se = 0.f;
    #pragma unroll
    for (int d = 0; d < 10; d++) se += expf(l[d] - mx);
    float lse = mx + logf(se);
    int lab = labels[idx % NNODE];
    atomicAdd(&g_loss, (double)(lse - l[lab]));

    const int FULL = TSTEPS*NNODE*11 + 1;  // preds + loss + lf
    if (out_size >= FULL) {
        out[idx] = (float)am;
        float* lf = out + TSTEPS*NNODE + 1 + (size_t)idx*10;
        #pragma unroll
        for (int d = 0; d < 10; d++) lf[d] = l[d];
    } else {
        float* lf = out + (size_t)idx*10;
        #pragma unroll
        for (int d = 0; d < 10; d++) lf[d] = l[d];
    }
}

__global__ void loss_kernel(float* __restrict__ out, int out_size)
{
    const int FULL = TSTEPS*NNODE*11 + 1;
    if (out_size >= FULL)
        out[TSTEPS*NNODE] = (float)(g_loss / (double)(TSTEPS*NNODE));
}

// ------------------------- launch -------------------------
extern "C" void kernel_launch(void* const* d_in, const int* in_sizes, int n_in,
                              void* d_out, int out_size)
{
    const int*   q      = (const int*)  d_in[0];
    const int*   row    = (const int*)  d_in[1];
    const int*   col    = (const int*)  d_in[2];
    const int*   labels = (const int*)  d_in[3];
    // d_in[4]=src, d_in[5]=dst : graph recomputed in-kernel, unused
    const float* d_emb  = (const float*)d_in[6];
    const float* r_emb  = (const float*)d_in[7];
    const float* c_emb  = (const float*)d_in[8];
    const float* in_W0  = (const float*)d_in[9];
    const float* in_W   = (const float*)d_in[10];
    const float* in_b   = (const float*)d_in[11];
    const float* msg_W0 = (const float*)d_in[12];
    const float* msg_W  = (const float*)d_in[13];
    const float* msg_b  = (const float*)d_in[14];
    const float* W_ih   = (const float*)d_in[15];
    const float* W_hh   = (const float*)d_in[16];
    const float* out_W  = (const float*)d_in[17];
    const float* out_b  = (const float*)d_in[18];
    float* out = (float*)d_out;

    const int IN_SMEM  = (48*96 + 3*9216 + 8*240) * 4;            // 136704 B
    const int MSG_SMEM = (3*9216 + 8*768) * 4 + 81*20*4;          // 141648 B
    cudaFuncSetAttribute(input_kernel, cudaFuncAttributeMaxDynamicSharedMemorySize, IN_SMEM);
    cudaFuncSetAttribute(msg_kernel,   cudaFuncAttributeMaxDynamicSharedMemorySize, MSG_SMEM);

    float *px, *pS1, *pm, *pgx, *pgm, *ph, *pWpack;
    cudaGetSymbolAddress((void**)&px,     g_x);
    cudaGetSymbolAddress((void**)&pS1,    g_S1);
    cudaGetSymbolAddress((void**)&pm,     g_m);
    cudaGetSymbolAddress((void**)&pgx,    g_gx);
    cudaGetSymbolAddress((void**)&pgm,    g_gm);
    cudaGetSymbolAddress((void**)&ph,     g_h);
    cudaGetSymbolAddress((void**)&pWpack, g_Wpack);

    pack_kernel<<<96, 256>>>(msg_W, in_W, in_W0, msg_W0, W_hh);
    input_kernel<<<152, 768, IN_SMEM>>>(q, row, col, d_emb, r_emb, c_emb, in_b);
    // gx = x @ W_ih[:, :96]^T  (step-invariant)
    sgemm_awt<<<dim3(384/64, NNODE/64), 256>>>(px, W_ih, pgx, 384, 192, 0);

    for (int t = 0; t < TSTEPS; t++) {
        // S1 = h @ [W0a; W0b; W_hh]^T  -> [a_src | a_dst | hW]
        sgemm_awt<<<dim3(576/64, NNODE/64), 256>>>(ph, pWpack, pS1, 576, 96, 0);
        msg_kernel<<<152, 768, MSG_SMEM>>>(msg_b);
        // gm = m @ W_ih[:, 96:]^T
        sgemm_awt<<<dim3(384/64, NNODE/64), 256>>>(pm, W_ih, pgm, 384, 192, 96);
        lstm_kernel<<<NNODE, 96>>>(out_W, out_b, t);
    }

    finalize_kernel<<<(TSTEPS*NNODE + 255)/256, 256>>>(labels, out, out_size);
    loss_kernel<<<1, 1>>>(out, out_size);
}

// round 4
// speedup vs baseline: 1.9226x; 1.9226x over previous
#include <cuda_runtime.h>
#include <cuda_bf16.h>
#include <math.h>
#include <stdint.h>

#define NB     128
#define NCELLS 81
#define NNODE  (NB*NCELLS)     // 10368
#define HD     96
#define TSTEPS 16
#define NTILES (NNODE/6)       // 1728 tiles of 6 nodes (120 edges + 8 pad)

// ========================= tf32 mma helpers (arch-agnostic, sm_80+) =========================
#define MMA1688(c,a0,a1,a2,a3,b0,b1) \
    asm volatile("mma.sync.aligned.m16n8k8.row.col.f32.tf32.tf32.f32 " \
        "{%0,%1,%2,%3}, {%4,%5,%6,%7}, {%8,%9}, {%0,%1,%2,%3};" \
        : "+f"((c)[0]),"+f"((c)[1]),"+f"((c)[2]),"+f"((c)[3]) \
        : "r"(a0),"r"(a1),"r"(a2),"r"(a3), "r"(b0),"r"(b1))

__device__ __forceinline__ uint32_t f2tf(float x) {
    uint32_t r; asm("cvt.rna.tf32.f32 %0, %1;" : "=r"(r) : "f"(x)); return r;
}
__device__ __forceinline__ float tf2f(uint32_t u) { return __uint_as_float(u); }

// ========================= device scratch =========================
__device__ float g_x[NNODE*HD];
__device__ float g_gx[NNODE*4*HD];
__device__ float g_S1[NNODE*6*HD];      // per-row: [a_src(96) | a_dst(96) | hW(384)]
__device__ float g_m[NNODE*HD];         // Z = sum of layer-2 activations over 20 edges
__device__ float g_gm[NNODE*4*HD];
__device__ float g_h[NNODE*HD];
__device__ float g_c[NNODE*HD];
__device__ float g_WTin[3*HD*HD];       // transposed in_W layers
__device__ float g_WTin0[48*HD];        // transposed in_W0
__device__ float g_Wpack[6*HD*HD];      // [576,96] = [W0a; W0b; W_hh]
__device__ float g_Wcomb[384*HD];       // W_ihm @ W3  [384,96]
__device__ float g_bc[384];             // 20 * W_ihm @ b3
__device__ float g_WT12[2*96*104];      // msg W1,W2 transposed (k-major), stride 104
__device__ float g_logits[(size_t)TSTEPS*NNODE*10];
__device__ double g_loss;

// ========================= weight packing =========================
__global__ void pack_kernel(const float* __restrict__ msg_W,
                            const float* __restrict__ in_W,
                            const float* __restrict__ in_W0,
                            const float* __restrict__ msg_W0,
                            const float* __restrict__ W_hh,
                            const float* __restrict__ W_ih,
                            const float* __restrict__ msg_b)
{
    int i = blockIdx.x*blockDim.x + threadIdx.x;
    int stride = gridDim.x*blockDim.x;
    for (int idx = i; idx < 3*HD*HD; idx += stride) {
        int l = idx / (HD*HD), r = idx % (HD*HD);
        int k = r / HD, j = r % HD;
        g_WTin[idx]  = in_W [l*HD*HD + j*HD + k];
    }
    for (int idx = i; idx < 48*HD; idx += stride) {
        int k = idx / HD, j = idx % HD;
        g_WTin0[idx] = in_W0[j*48 + k];
    }
    for (int idx = i; idx < 576*HD; idx += stride) {
        int o = idx / HD, k = idx % HD;
        float v;
        if (o < 96)       v = msg_W0[o*192 + k];            // W0a (src half)
        else if (o < 192) v = msg_W0[(o-96)*192 + 96 + k];  // W0b (dst half)
        else              v = W_hh[(o-192)*HD + k];
        g_Wpack[idx] = v;
    }
    // k-major fp32 transposed images of msg layers 1,2: WT[k][j], stride 104
    for (int idx = i; idx < 2*96*104; idx += stride) {
        int l = idx / (96*104), r2 = idx % (96*104);
        int k = r2 / 104, j = r2 % 104;
        g_WT12[idx] = (j < 96) ? msg_W[l*HD*HD + j*HD + k] : 0.f;
    }
    // Wcomb[o][k] = sum_c W_ihm[o][c] * W3[c][k]
    for (int idx = i; idx < 384*HD; idx += stride) {
        int o = idx/HD, k = idx%HD;
        float s = 0.f;
        const float* wm = W_ih + o*192 + 96;
        const float* w3 = msg_W + 2*HD*HD + k;
        #pragma unroll 8
        for (int c = 0; c < 96; c++) s = fmaf(wm[c], w3[c*96], s);
        g_Wcomb[idx] = s;
    }
    for (int idx = i; idx < 384; idx += stride) {
        float s = 0.f;
        #pragma unroll 8
        for (int c = 0; c < 96; c++) s = fmaf(W_ih[idx*192+96+c], msg_b[288+c], s);
        g_bc[idx] = 20.f * s;
    }
    if (i == 0) g_loss = 0.0;
}

// ========================= fp32 sgemm: C = A @ W^T =========================
__global__ void __launch_bounds__(256) sgemm_awt(const float* __restrict__ A,
                                                 const float* __restrict__ W,
                                                 float* __restrict__ C,
                                                 int Nc, int ldw, int woff)
{
    __shared__ float As[16][65];
    __shared__ float Ws[16][65];
    int bm = blockIdx.y * 64, bn = blockIdx.x * 64;
    int tid = threadIdx.x;
    int tx = tid & 15, ty = tid >> 4;
    int lr = tid >> 2, lk = (tid & 3) << 2;
    float acc[4][4];
    #pragma unroll
    for (int i = 0; i < 4; i++)
        #pragma unroll
        for (int j = 0; j < 4; j++) acc[i][j] = 0.f;

    for (int k0 = 0; k0 < 96; k0 += 16) {
        float4 a = *(const float4*)(A + (size_t)(bm+lr)*96 + k0 + lk);
        As[lk+0][lr]=a.x; As[lk+1][lr]=a.y; As[lk+2][lr]=a.z; As[lk+3][lr]=a.w;
        float4 w = *(const float4*)(W + (size_t)(bn+lr)*ldw + woff + k0 + lk);
        Ws[lk+0][lr]=w.x; Ws[lk+1][lr]=w.y; Ws[lk+2][lr]=w.z; Ws[lk+3][lr]=w.w;
        __syncthreads();
        #pragma unroll
        for (int k = 0; k < 16; k++) {
            float av[4], wv[4];
            #pragma unroll
            for (int i = 0; i < 4; i++) av[i] = As[k][ty*4+i];
            #pragma unroll
            for (int j = 0; j < 4; j++) wv[j] = Ws[k][tx*4+j];
            #pragma unroll
            for (int i = 0; i < 4; i++)
                #pragma unroll
                for (int j = 0; j < 4; j++)
                    acc[i][j] = fmaf(av[i], wv[j], acc[i][j]);
        }
        __syncthreads();
    }
    #pragma unroll
    for (int i = 0; i < 4; i++) {
        float4 o = make_float4(acc[i][0], acc[i][1], acc[i][2], acc[i][3]);
        *(float4*)(C + (size_t)(bm + ty*4 + i)*Nc + bn + tx*4) = o;
    }
}

// ========================= input embedding + MLP =========================
__device__ __forceinline__ float dot96(const float* __restrict__ WTcol,
                                       const float* __restrict__ vin)
{
    float s = 0.f;
    #pragma unroll 8
    for (int k4 = 0; k4 < 24; k4++) {
        float4 a = ((const float4*)vin)[k4];
        s = fmaf(WTcol[(4*k4+0)*96], a.x, s);
        s = fmaf(WTcol[(4*k4+1)*96], a.y, s);
        s = fmaf(WTcol[(4*k4+2)*96], a.z, s);
        s = fmaf(WTcol[(4*k4+3)*96], a.w, s);
    }
    return s;
}

__global__ void __launch_bounds__(768) input_kernel(const int* __restrict__ q,
    const int* __restrict__ rw, const int* __restrict__ cl,
    const float* __restrict__ demb, const float* __restrict__ remb,
    const float* __restrict__ cemb, const float* __restrict__ inb)
{
    extern __shared__ float sm[];
    float* sW0 = sm;
    float* sWT = sm + 48*96;
    float* svb = sWT + 3*9216;
    for (int i = threadIdx.x; i < 48*96;  i += 768) sW0[i] = g_WTin0[i];
    for (int i = threadIdx.x; i < 3*9216; i += 768) sWT[i] = g_WTin[i];
    __syncthreads();

    int slot = threadIdx.x / 96, j = threadIdx.x % 96;
    float* v0 = svb + slot*240;
    float* vA = v0 + 48;
    float* vB = vA + 96;
    int sg = blockIdx.x*8 + slot;
    int stride = gridDim.x*8;
    int iters = (NNODE + stride - 1) / stride;
    float b0 = inb[j], b1 = inb[96+j], b2 = inb[192+j], b3 = inb[288+j];

    for (int it = 0; it < iters; it++) {
        int node = sg + it*stride;
        bool act = node < NNODE;
        int n = act ? node : NNODE-1;
        if (j < 16)      v0[j] = demb[q[n]*16 + j];
        else if (j < 32) v0[j] = remb[rw[n]*16 + (j-16)];
        else if (j < 48) v0[j] = cemb[cl[n]*16 + (j-32)];
        __syncthreads();
        float s = b0;
        #pragma unroll
        for (int k4 = 0; k4 < 12; k4++) {
            float4 a = ((const float4*)v0)[k4];
            s = fmaf(sW0[(4*k4+0)*96+j], a.x, s);
            s = fmaf(sW0[(4*k4+1)*96+j], a.y, s);
            s = fmaf(sW0[(4*k4+2)*96+j], a.z, s);
            s = fmaf(sW0[(4*k4+3)*96+j], a.w, s);
        }
        vA[j] = fmaxf(s, 0.f);
        __syncthreads();
        float t1 = b1 + dot96(sWT + j, vA);
        vB[j] = fmaxf(t1, 0.f);
        __syncthreads();
        float t2 = b2 + dot96(sWT + 9216 + j, vB);
        vA[j] = fmaxf(t2, 0.f);
        __syncthreads();
        float t3 = b3 + dot96(sWT + 2*9216 + j, vA);
        if (act) {
            g_x[(size_t)node*96 + j] = t3;
            g_h[(size_t)node*96 + j] = t3;   // h0 = x
            g_c[(size_t)node*96 + j] = 0.f;  // c0 = 0
        }
        __syncthreads();
    }
}

// ========================= tf32 HMMA edge pipeline =========================
// smem (bytes):
#define OFF_B0     0               // 96 floats
#define OFF_B1     384
#define OFF_B2     768
#define OFF_NBR    1152            // 81*20 ints -> ends 7632
#define OFF_W      7680            // 2 x (96 x 104) floats = 79,872 B
#define OFF_A      87552           // 128 x 100 floats = 51,200 B
#define EK_SMEM    138752
#define WST        104             // W row stride (floats) — conflict-free B frags
#define AST        100             // A row stride (floats) — conflict-free A frags
#define WMATF      (96*104)

// one layer via 3xTF32: acc[12][4] += A @ W^T, split hi/lo on the fly
__device__ __forceinline__ void run_layer_tf32(const float* __restrict__ pa0,
                                               const float* __restrict__ pa1,
                                               const float* __restrict__ pb,
                                               float acc[12][4])
{
    #pragma unroll 1
    for (int kt = 0; kt < 12; kt++) {
        float va0 = pa0[kt*8],   va2 = pa0[kt*8+4];
        float va1 = pa1[kt*8],   va3 = pa1[kt*8+4];
        uint32_t ah0=f2tf(va0), ah1=f2tf(va1), ah2=f2tf(va2), ah3=f2tf(va3);
        uint32_t al0=f2tf(va0-tf2f(ah0)), al1=f2tf(va1-tf2f(ah1));
        uint32_t al2=f2tf(va2-tf2f(ah2)), al3=f2tf(va3-tf2f(ah3));
        const float* pbk = pb + kt*8*WST;
        #pragma unroll
        for (int nt = 0; nt < 12; nt++) {
            float vb0 = pbk[nt*8], vb1 = pbk[nt*8 + 4*WST];
            uint32_t bh0=f2tf(vb0), bh1=f2tf(vb1);
            uint32_t bl0=f2tf(vb0-tf2f(bh0)), bl1=f2tf(vb1-tf2f(bh1));
            MMA1688(acc[nt], ah0,ah1,ah2,ah3, bh0,bh1);
            MMA1688(acc[nt], al0,al1,al2,al3, bh0,bh1);
            MMA1688(acc[nt], ah0,ah1,ah2,ah3, bl0,bl1);
        }
    }
}

__global__ void __launch_bounds__(256) edge_tc_kernel(const float* __restrict__ msgb)
{
    extern __shared__ char smc[];
    float* sb0 = (float*)(smc + OFF_B0);
    float* sb1 = (float*)(smc + OFF_B1);
    float* sb2 = (float*)(smc + OFF_B2);
    int*  snbr = (int*)(smc + OFF_NBR);
    float* sW  = (float*)(smc + OFF_W);
    float* sA  = (float*)(smc + OFF_A);
    int tid = threadIdx.x, lane = tid & 31, wid = tid >> 5;

    if (tid < 96) { sb0[tid]=msgb[tid]; sb1[tid]=msgb[96+tid]; sb2[tid]=msgb[192+tid]; }
    if (tid < 81) {
        int u = tid;
        int ru = u/9, cu = u%9, bu = (ru/3)*3 + cu/3;
        int cnt = 0;
        for (int v = 0; v < 81; v++) {
            if (v == u) continue;
            int rv = v/9, cv = v%9, bv = (rv/3)*3 + cv/3;
            if (rv == ru || cv == cu || bv == bu) snbr[u*20 + cnt++] = v;
        }
    }
    for (int i = tid; i < 2*WMATF/4; i += 256)
        ((float4*)sW)[i] = ((const float4*)g_WT12)[i];
    __syncthreads();

    // fragment pointers (m16n8k8 tf32 layout)
    const float* pa0 = sA + (wid*16 + (lane>>2))*AST + (lane&3);
    const float* pa1 = pa0 + 8*AST;
    const float* pb1 = sW + (lane&3)*WST + (lane>>2);
    const float* pb2 = pb1 + WMATF;
    int cb = (lane & 3) * 2;
    int r0 = wid*16 + (lane >> 2);
    int rA = tid & 127, half = tid >> 7;

    for (int g = blockIdx.x; g < NTILES; g += gridDim.x) {
        // ---- build E0 = relu(a_src + a_dst + b0) as fp32 into A smem ----
        float* dst = sA + rA*AST + half*48;
        if (rA < 120) {
            int dnode = g*6 + rA/20;
            int cell = dnode % 81;
            int srcn = dnode - cell + snbr[cell*20 + (rA % 20)];
            const float4* aS = (const float4*)(g_S1 + (size_t)srcn*576 + half*48);
            const float4* aD = (const float4*)(g_S1 + (size_t)dnode*576 + 96 + half*48);
            const float4* bB = (const float4*)(sb0 + half*48);
            #pragma unroll 3
            for (int k4 = 0; k4 < 12; k4++) {
                float4 s = aS[k4], dd = aD[k4], bb = bB[k4];
                float4 o;
                o.x = fmaxf(s.x+dd.x+bb.x, 0.f);
                o.y = fmaxf(s.y+dd.y+bb.y, 0.f);
                o.z = fmaxf(s.z+dd.z+bb.z, 0.f);
                o.w = fmaxf(s.w+dd.w+bb.w, 0.f);
                ((float4*)dst)[k4] = o;
            }
        } else {
            #pragma unroll 3
            for (int k4 = 0; k4 < 12; k4++)
                ((float4*)dst)[k4] = make_float4(0.f,0.f,0.f,0.f);
        }
        __syncthreads();

        // ---- layer 1 ----
        float acc[12][4];
        #pragma unroll
        for (int nt = 0; nt < 12; nt++) {
            float bA = sb1[nt*8 + cb], bB2 = sb1[nt*8 + cb + 1];
            acc[nt][0]=bA; acc[nt][1]=bB2; acc[nt][2]=bA; acc[nt][3]=bB2;
        }
        run_layer_tf32(pa0, pa1, pb1, acc);
        __syncthreads();
        // epilogue 1: relu -> fp32 back into A smem
        #pragma unroll
        for (int nt = 0; nt < 12; nt++) {
            int c = nt*8 + cb;
            float2 vlo = make_float2(fmaxf(acc[nt][0],0.f), fmaxf(acc[nt][1],0.f));
            float2 vhi = make_float2(fmaxf(acc[nt][2],0.f), fmaxf(acc[nt][3],0.f));
            *(float2*)(sA + r0*AST + c)     = vlo;
            *(float2*)(sA + (r0+8)*AST + c) = vhi;
        }
        __syncthreads();

        // ---- layer 2 ----
        #pragma unroll
        for (int nt = 0; nt < 12; nt++) {
            float bA = sb2[nt*8 + cb], bB2 = sb2[nt*8 + cb + 1];
            acc[nt][0]=bA; acc[nt][1]=bB2; acc[nt][2]=bA; acc[nt][3]=bB2;
        }
        run_layer_tf32(pa0, pa1, pb2, acc);
        __syncthreads();
        // epilogue 2: relu -> stage (stride 97, aliases A), then per-node sum
        float* stg = sA;
        #pragma unroll
        for (int nt = 0; nt < 12; nt++) {
            int c = nt*8 + cb;
            stg[r0*97 + c]       = fmaxf(acc[nt][0], 0.f);
            stg[r0*97 + c + 1]   = fmaxf(acc[nt][1], 0.f);
            stg[(r0+8)*97 + c]   = fmaxf(acc[nt][2], 0.f);
            stg[(r0+8)*97 + c+1] = fmaxf(acc[nt][3], 0.f);
        }
        __syncthreads();
        for (int idx = tid; idx < 576; idx += 256) {
            int i = idx / 96, c = idx % 96;
            float s = 0.f;
            #pragma unroll
            for (int e = 0; e < 20; e++) s += stg[(i*20+e)*97 + c];
            g_m[(size_t)(g*6+i)*96 + c] = s;
        }
        __syncthreads();
    }
}

// ========================= LSTM pointwise + per-step logits =========================
__global__ void __launch_bounds__(96) lstm_kernel(const float* __restrict__ outW,
                                                  const float* __restrict__ outb, int t)
{
    int n = blockIdx.x, j = threadIdx.x;
    __shared__ float sh[HD];
    size_t b4 = (size_t)n*384 + j;
    float gi = g_gx[b4      ] + g_gm[b4      ] + g_bc[j];
    float gf = g_gx[b4 +  96] + g_gm[b4 +  96] + g_bc[96+j];
    float gg = g_gx[b4 + 192] + g_gm[b4 + 192] + g_bc[192+j];
    float go = g_gx[b4 + 288] + g_gm[b4 + 288] + g_bc[288+j];
    if (t > 0) {
        const float* hw = g_S1 + (size_t)n*576 + 192 + j;
        gi += hw[0]; gf += hw[96]; gg += hw[192]; go += hw[288];
    }
    float si = 1.f/(1.f + expf(-gi));
    float sf = 1.f/(1.f + expf(-gf));
    float so = 1.f/(1.f + expf(-go));
    float cn = sf * g_c[(size_t)n*96 + j] + si * tanhf(gg);
    float hn = so * tanhf(cn);
    g_c[(size_t)n*96 + j] = cn;
    g_h[(size_t)n*96 + j] = hn;
    sh[j] = hn;
    __syncthreads();
    if (j < 10) {
        float s = outb[j];
        const float* w = outW + j*96;
        #pragma unroll 8
        for (int k = 0; k < 96; k++) s = fmaf(sh[k], w[k], s);
        g_logits[((size_t)t*NNODE + n)*10 + j] = s;
    }
}

// ========================= preds / loss / lf =========================
__global__ void finalize_kernel(const int* __restrict__ labels,
                                float* __restrict__ out, int out_size)
{
    int idx = blockIdx.x*blockDim.x + threadIdx.x;
    double term = 0.0;
    if (idx < TSTEPS*NNODE) {
        const float* l = g_logits + (size_t)idx*10;
        float mx = l[0]; int am = 0;
        #pragma unroll
        for (int d = 1; d < 10; d++) if (l[d] > mx) { mx = l[d]; am = d; }
        float se = 0.f;
        #pragma unroll
        for (int d = 0; d < 10; d++) se += expf(l[d] - mx);
        float lse = mx + logf(se);
        int lab = labels[idx % NNODE];
        term = (double)(lse - l[lab]);

        const int FULL = TSTEPS*NNODE*11 + 1;  // preds + loss + lf
        if (out_size >= FULL) {
            out[idx] = (float)am;
            float* lf = out + TSTEPS*NNODE + 1 + (size_t)idx*10;
            #pragma unroll
            for (int d = 0; d < 10; d++) lf[d] = l[d];
        } else {
            float* lf = out + (size_t)idx*10;
            #pragma unroll
            for (int d = 0; d < 10; d++) lf[d] = l[d];
        }
    }
    // warp-reduced loss accumulation
    #pragma unroll
    for (int o = 16; o; o >>= 1)
        term += __shfl_down_sync(0xffffffffu, term, o);
    if ((threadIdx.x & 31) == 0 && term != 0.0) atomicAdd(&g_loss, term);
}

__global__ void loss_kernel(float* __restrict__ out, int out_size)
{
    const int FULL = TSTEPS*NNODE*11 + 1;
    if (out_size >= FULL)
        out[TSTEPS*NNODE] = (float)(g_loss / (double)(TSTEPS*NNODE));
}

// ========================= launch =========================
extern "C" void kernel_launch(void* const* d_in, const int* in_sizes, int n_in,
                              void* d_out, int out_size)
{
    const int*   q      = (const int*)  d_in[0];
    const int*   row    = (const int*)  d_in[1];
    const int*   col    = (const int*)  d_in[2];
    const int*   labels = (const int*)  d_in[3];
    const float* d_emb  = (const float*)d_in[6];
    const float* r_emb  = (const float*)d_in[7];
    const float* c_emb  = (const float*)d_in[8];
    const float* in_W0  = (const float*)d_in[9];
    const float* in_W   = (const float*)d_in[10];
    const float* in_b   = (const float*)d_in[11];
    const float* msg_W0 = (const float*)d_in[12];
    const float* msg_W  = (const float*)d_in[13];
    const float* msg_b  = (const float*)d_in[14];
    const float* W_ih   = (const float*)d_in[15];
    const float* W_hh   = (const float*)d_in[16];
    const float* out_W  = (const float*)d_in[17];
    const float* out_b  = (const float*)d_in[18];
    float* out = (float*)d_out;

    const int IN_SMEM = (48*96 + 3*9216 + 8*240) * 4;
    cudaFuncSetAttribute(input_kernel,   cudaFuncAttributeMaxDynamicSharedMemorySize, IN_SMEM);
    cudaFuncSetAttribute(edge_tc_kernel, cudaFuncAttributeMaxDynamicSharedMemorySize, EK_SMEM);

    float *px, *pS1, *pm, *pgx, *pgm, *ph, *pWpack, *pWcomb;
    cudaGetSymbolAddress((void**)&px,     g_x);
    cudaGetSymbolAddress((void**)&pS1,    g_S1);
    cudaGetSymbolAddress((void**)&pm,     g_m);
    cudaGetSymbolAddress((void**)&pgx,    g_gx);
    cudaGetSymbolAddress((void**)&pgm,    g_gm);
    cudaGetSymbolAddress((void**)&ph,     g_h);
    cudaGetSymbolAddress((void**)&pWpack, g_Wpack);
    cudaGetSymbolAddress((void**)&pWcomb, g_Wcomb);

    pack_kernel<<<192, 256>>>(msg_W, in_W, in_W0, msg_W0, W_hh, W_ih, msg_b);
    input_kernel<<<152, 768, IN_SMEM>>>(q, row, col, d_emb, r_emb, c_emb, in_b);
    // gx = x @ W_ih[:, :96]^T  (step-invariant)
    sgemm_awt<<<dim3(384/64, NNODE/64), 256>>>(px, W_ih, pgx, 384, 192, 0);

    for (int t = 0; t < TSTEPS; t++) {
        // S1 = h @ [W0a; W0b; W_hh]^T  -> [a_src | a_dst | hW]
        sgemm_awt<<<dim3(576/64, NNODE/64), 256>>>(ph, pWpack, pS1, 576, 96, 0);
        edge_tc_kernel<<<152, 256, EK_SMEM>>>(msg_b);
        // gm = Z @ (W_ihm @ W3)^T   (+bc added in lstm)
        sgemm_awt<<<dim3(384/64, NNODE/64), 256>>>(pm, pWcomb, pgm, 384, 96, 0);
        lstm_kernel<<<NNODE, 96>>>(out_W, out_b, t);
    }

    finalize_kernel<<<(TSTEPS*NNODE + 255)/256, 256>>>(labels, out, out_size);
    loss_kernel<<<1, 1>>>(out, out_size);
}

// round 5
// speedup vs baseline: 2.2895x; 1.1908x over previous
#include <cuda_runtime.h>
#include <cuda_bf16.h>
#include <math.h>
#include <stdint.h>

#define NB     128
#define NCELLS 81
#define NNODE  (NB*NCELLS)     // 10368
#define HD     96
#define TSTEPS 16
#define NTILES (NNODE/6)       // 1728 tiles of 6 nodes (120 edges + 8 pad)

// ========================= tf32 mma helpers (arch-agnostic, sm_80+) =========================
#define MMA1688(c,a0,a1,a2,a3,b0,b1) \
    asm volatile("mma.sync.aligned.m16n8k8.row.col.f32.tf32.tf32.f32 " \
        "{%0,%1,%2,%3}, {%4,%5,%6,%7}, {%8,%9}, {%0,%1,%2,%3};" \
        : "+f"((c)[0]),"+f"((c)[1]),"+f"((c)[2]),"+f"((c)[3]) \
        : "r"(a0),"r"(a1),"r"(a2),"r"(a3), "r"(b0),"r"(b1))

__device__ __forceinline__ uint32_t f2tf(float x) {
    uint32_t r; asm("cvt.rna.tf32.f32 %0, %1;" : "=r"(r) : "f"(x)); return r;
}
__device__ __forceinline__ float tf2f(uint32_t u) { return __uint_as_float(u); }

#define WST    104             // W image row stride (floats) — conflict-free frags
#define AST    100             // A row stride (floats) — conflict-free frags
#define WMATF  (96*104)

// ========================= device scratch =========================
__device__ float g_x[NNODE*HD];
__device__ float g_gx[NNODE*4*HD];
__device__ float g_S1[NNODE*6*HD];      // per-row: [a_src(96) | a_dst(96) | hW(384)]
__device__ float g_m[NNODE*HD];         // Z = sum of layer-2 activations over 20 edges
__device__ float g_gm[NNODE*4*HD];
__device__ float g_h[NNODE*HD];
__device__ float g_c[NNODE*HD];
__device__ float g_WTin[3*HD*HD];       // transposed in_W layers
__device__ float g_WTin0[48*HD];        // transposed in_W0
__device__ float g_Wpack[6*HD*HD];      // [576,96] = [W0a; W0b; W_hh]
__device__ float g_Wcomb[384*HD];       // W_ihm @ W3  [384,96]
__device__ float g_bc[384];             // 20 * W_ihm @ b3
__device__ float g_Wsplit[4*WMATF];     // [W1hi | W1lo | W2hi | W2lo] k-major, stride 104
__device__ float g_logits[(size_t)TSTEPS*NNODE*10];
__device__ double g_loss;

// ========================= weight packing =========================
__global__ void pack_kernel(const float* __restrict__ msg_W,
                            const float* __restrict__ in_W,
                            const float* __restrict__ in_W0,
                            const float* __restrict__ msg_W0,
                            const float* __restrict__ W_hh,
                            const float* __restrict__ W_ih,
                            const float* __restrict__ msg_b)
{
    int i = blockIdx.x*blockDim.x + threadIdx.x;
    int stride = gridDim.x*blockDim.x;
    for (int idx = i; idx < 3*HD*HD; idx += stride) {
        int l = idx / (HD*HD), r = idx % (HD*HD);
        int k = r / HD, j = r % HD;
        g_WTin[idx]  = in_W [l*HD*HD + j*HD + k];
    }
    for (int idx = i; idx < 48*HD; idx += stride) {
        int k = idx / HD, j = idx % HD;
        g_WTin0[idx] = in_W0[j*48 + k];
    }
    for (int idx = i; idx < 576*HD; idx += stride) {
        int o = idx / HD, k = idx % HD;
        float v;
        if (o < 96)       v = msg_W0[o*192 + k];            // W0a (src half)
        else if (o < 192) v = msg_W0[(o-96)*192 + 96 + k];  // W0b (dst half)
        else              v = W_hh[(o-192)*HD + k];
        g_Wpack[idx] = v;
    }
    // k-major tf32 hi/lo images of msg layers 1,2: WT[k][j], stride 104
    for (int idx = i; idx < 4*WMATF; idx += stride) {
        int part = idx / WMATF;             // 0=W1hi 1=W1lo 2=W2hi 3=W2lo
        int r2 = idx % WMATF;
        int k = r2 / WST, j = r2 % WST;
        int layer = part >> 1, which = part & 1;
        float w = (j < 96) ? msg_W[layer*HD*HD + j*HD + k] : 0.f;
        float hi = tf2f(f2tf(w));
        g_Wsplit[idx] = which ? tf2f(f2tf(w - hi)) : hi;
    }
    // Wcomb[o][k] = sum_c W_ihm[o][c] * W3[c][k]
    for (int idx = i; idx < 384*HD; idx += stride) {
        int o = idx/HD, k = idx%HD;
        float s = 0.f;
        const float* wm = W_ih + o*192 + 96;
        const float* w3 = msg_W + 2*HD*HD + k;
        #pragma unroll 8
        for (int c = 0; c < 96; c++) s = fmaf(wm[c], w3[c*96], s);
        g_Wcomb[idx] = s;
    }
    for (int idx = i; idx < 384; idx += stride) {
        float s = 0.f;
        #pragma unroll 8
        for (int c = 0; c < 96; c++) s = fmaf(W_ih[idx*192+96+c], msg_b[288+c], s);
        g_bc[idx] = 20.f * s;
    }
    if (i == 0) g_loss = 0.0;
}

// ========================= fp32 sgemm: C = A @ W^T =========================
__global__ void __launch_bounds__(256) sgemm_awt(const float* __restrict__ A,
                                                 const float* __restrict__ W,
                                                 float* __restrict__ C,
                                                 int Nc, int ldw, int woff)
{
    __shared__ float As[16][68];
    __shared__ float Ws[16][68];
    int bm = blockIdx.y * 64, bn = blockIdx.x * 64;
    int tid = threadIdx.x;
    int tx = tid & 15, ty = tid >> 4;
    int lr = tid >> 2, lk = (tid & 3) << 2;
    float acc[4][4];
    #pragma unroll
    for (int i = 0; i < 4; i++)
        #pragma unroll
        for (int j = 0; j < 4; j++) acc[i][j] = 0.f;

    for (int k0 = 0; k0 < 96; k0 += 16) {
        float4 a = *(const float4*)(A + (size_t)(bm+lr)*96 + k0 + lk);
        As[lk+0][lr]=a.x; As[lk+1][lr]=a.y; As[lk+2][lr]=a.z; As[lk+3][lr]=a.w;
        float4 w = *(const float4*)(W + (size_t)(bn+lr)*ldw + woff + k0 + lk);
        Ws[lk+0][lr]=w.x; Ws[lk+1][lr]=w.y; Ws[lk+2][lr]=w.z; Ws[lk+3][lr]=w.w;
        __syncthreads();
        #pragma unroll
        for (int k = 0; k < 16; k++) {
            float4 a4 = *(const float4*)&As[k][ty*4];
            float4 w4 = *(const float4*)&Ws[k][tx*4];
            float av[4] = {a4.x, a4.y, a4.z, a4.w};
            float wv[4] = {w4.x, w4.y, w4.z, w4.w};
            #pragma unroll
            for (int i = 0; i < 4; i++)
                #pragma unroll
                for (int j = 0; j < 4; j++)
                    acc[i][j] = fmaf(av[i], wv[j], acc[i][j]);
        }
        __syncthreads();
    }
    #pragma unroll
    for (int i = 0; i < 4; i++) {
        float4 o = make_float4(acc[i][0], acc[i][1], acc[i][2], acc[i][3]);
        *(float4*)(C + (size_t)(bm + ty*4 + i)*Nc + bn + tx*4) = o;
    }
}

// ========================= input embedding + MLP =========================
__device__ __forceinline__ float dot96(const float* __restrict__ WTcol,
                                       const float* __restrict__ vin)
{
    float s = 0.f;
    #pragma unroll 8
    for (int k4 = 0; k4 < 24; k4++) {
        float4 a = ((const float4*)vin)[k4];
        s = fmaf(WTcol[(4*k4+0)*96], a.x, s);
        s = fmaf(WTcol[(4*k4+1)*96], a.y, s);
        s = fmaf(WTcol[(4*k4+2)*96], a.z, s);
        s = fmaf(WTcol[(4*k4+3)*96], a.w, s);
    }
    return s;
}

__global__ void __launch_bounds__(768) input_kernel(const int* __restrict__ q,
    const int* __restrict__ rw, const int* __restrict__ cl,
    const float* __restrict__ demb, const float* __restrict__ remb,
    const float* __restrict__ cemb, const float* __restrict__ inb)
{
    extern __shared__ float sm[];
    float* sW0 = sm;
    float* sWT = sm + 48*96;
    float* svb = sWT + 3*9216;
    for (int i = threadIdx.x; i < 48*96;  i += 768) sW0[i] = g_WTin0[i];
    for (int i = threadIdx.x; i < 3*9216; i += 768) sWT[i] = g_WTin[i];
    __syncthreads();

    int slot = threadIdx.x / 96, j = threadIdx.x % 96;
    float* v0 = svb + slot*240;
    float* vA = v0 + 48;
    float* vB = vA + 96;
    int sg = blockIdx.x*8 + slot;
    int stride = gridDim.x*8;
    int iters = (NNODE + stride - 1) / stride;
    float b0 = inb[j], b1 = inb[96+j], b2 = inb[192+j], b3 = inb[288+j];

    for (int it = 0; it < iters; it++) {
        int node = sg + it*stride;
        bool act = node < NNODE;
        int n = act ? node : NNODE-1;
        if (j < 16)      v0[j] = demb[q[n]*16 + j];
        else if (j < 32) v0[j] = remb[rw[n]*16 + (j-16)];
        else if (j < 48) v0[j] = cemb[cl[n]*16 + (j-32)];
        __syncthreads();
        float s = b0;
        #pragma unroll
        for (int k4 = 0; k4 < 12; k4++) {
            float4 a = ((const float4*)v0)[k4];
            s = fmaf(sW0[(4*k4+0)*96+j], a.x, s);
            s = fmaf(sW0[(4*k4+1)*96+j], a.y, s);
            s = fmaf(sW0[(4*k4+2)*96+j], a.z, s);
            s = fmaf(sW0[(4*k4+3)*96+j], a.w, s);
        }
        vA[j] = fmaxf(s, 0.f);
        __syncthreads();
        float t1 = b1 + dot96(sWT + j, vA);
        vB[j] = fmaxf(t1, 0.f);
        __syncthreads();
        float t2 = b2 + dot96(sWT + 9216 + j, vB);
        vA[j] = fmaxf(t2, 0.f);
        __syncthreads();
        float t3 = b3 + dot96(sWT + 2*9216 + j, vA);
        if (act) {
            g_x[(size_t)node*96 + j] = t3;
            g_h[(size_t)node*96 + j] = t3;   // h0 = x
            g_c[(size_t)node*96 + j] = 0.f;  // c0 = 0
        }
        __syncthreads();
    }
}

// ========================= tf32 HMMA edge pipeline =========================
// smem (bytes):
#define OFF_B0     0               // 96 floats
#define OFF_B1     384
#define OFF_B2     768
#define OFF_NBR    1152            // 81*20 ints -> ends 7632
#define OFF_W      7680            // 4 x (96 x 104) floats = 159,744 B
#define OFF_A      167424          // 128 x 100 floats = 51,200 B
#define EK_SMEM    218624

// one layer via 3xTF32 (weights pre-split): acc[6][4] += A @ W^T (this warp's n48 half)
__device__ __forceinline__ void run_layer_tf32(const float* __restrict__ pa0,
                                               const float* __restrict__ pa1,
                                               const float* __restrict__ pbh,
                                               const float* __restrict__ pbl,
                                               float acc[6][4])
{
    #pragma unroll 1
    for (int kt = 0; kt < 12; kt++) {
        float va0 = pa0[kt*8],   va2 = pa0[kt*8+4];
        float va1 = pa1[kt*8],   va3 = pa1[kt*8+4];
        uint32_t ah0=f2tf(va0), ah1=f2tf(va1), ah2=f2tf(va2), ah3=f2tf(va3);
        uint32_t al0=f2tf(va0-tf2f(ah0)), al1=f2tf(va1-tf2f(ah1));
        uint32_t al2=f2tf(va2-tf2f(ah2)), al3=f2tf(va3-tf2f(ah3));
        const float* ph = pbh + kt*8*WST;
        const float* pl = pbl + kt*8*WST;
        #pragma unroll
        for (int nt = 0; nt < 6; nt++) {
            uint32_t bh0 = __float_as_uint(ph[nt*8]);
            uint32_t bh1 = __float_as_uint(ph[nt*8 + 4*WST]);
            uint32_t bl0 = __float_as_uint(pl[nt*8]);
            uint32_t bl1 = __float_as_uint(pl[nt*8 + 4*WST]);
            MMA1688(acc[nt], ah0,ah1,ah2,ah3, bh0,bh1);
            MMA1688(acc[nt], al0,al1,al2,al3, bh0,bh1);
            MMA1688(acc[nt], ah0,ah1,ah2,ah3, bl0,bl1);
        }
    }
}

__global__ void __launch_bounds__(512) edge_tc_kernel(const float* __restrict__ msgb)
{
    extern __shared__ char smc[];
    float* sb0 = (float*)(smc + OFF_B0);
    float* sb1 = (float*)(smc + OFF_B1);
    float* sb2 = (float*)(smc + OFF_B2);
    int*  snbr = (int*)(smc + OFF_NBR);
    float* sW  = (float*)(smc + OFF_W);
    float* sA  = (float*)(smc + OFF_A);
    int tid = threadIdx.x, lane = tid & 31, wid = tid >> 5;

    if (tid < 96) { sb0[tid]=msgb[tid]; sb1[tid]=msgb[96+tid]; sb2[tid]=msgb[192+tid]; }
    if (tid < 81) {
        int u = tid;
        int ru = u/9, cu = u%9, bu = (ru/3)*3 + cu/3;
        int cnt = 0;
        for (int v = 0; v < 81; v++) {
            if (v == u) continue;
            int rv = v/9, cv = v%9, bv = (rv/3)*3 + cv/3;
            if (rv == ru || cv == cu || bv == bu) snbr[u*20 + cnt++] = v;
        }
    }
    for (int i = tid; i < 4*WMATF/4; i += 512)
        ((float4*)sW)[i] = ((const float4*)g_Wsplit)[i];
    __syncthreads();

    // fragment pointers: warp = (mtile, nhalf)
    int mtile = wid >> 1, nhalf = wid & 1;
    const float* pa0 = sA + (mtile*16 + (lane>>2))*AST + (lane&3);
    const float* pa1 = pa0 + 8*AST;
    int foff = (lane&3)*WST + (lane>>2) + nhalf*48;
    const float* pb1h = sW + 0*WMATF + foff;
    const float* pb1l = sW + 1*WMATF + foff;
    const float* pb2h = sW + 2*WMATF + foff;
    const float* pb2l = sW + 3*WMATF + foff;
    int cb = (lane & 3) * 2;
    int r0 = mtile*16 + (lane >> 2);
    int rA = tid & 127, part = tid >> 7;   // A-build: row, col-quarter (24 cols)

    for (int g = blockIdx.x; g < NTILES; g += gridDim.x) {
        // ---- build E0 = relu(a_src + a_dst + b0) as fp32 into A smem ----
        float* dst = sA + rA*AST + part*24;
        if (rA < 120) {
            int dnode = g*6 + rA/20;
            int cell = dnode % 81;
            int srcn = dnode - cell + snbr[cell*20 + (rA % 20)];
            const float4* aS = (const float4*)(g_S1 + (size_t)srcn*576 + part*24);
            const float4* aD = (const float4*)(g_S1 + (size_t)dnode*576 + 96 + part*24);
            const float4* bB = (const float4*)(sb0 + part*24);
            #pragma unroll
            for (int k4 = 0; k4 < 6; k4++) {
                float4 s = aS[k4], dd = aD[k4], bb = bB[k4];
                float4 o;
                o.x = fmaxf(s.x+dd.x+bb.x, 0.f);
                o.y = fmaxf(s.y+dd.y+bb.y, 0.f);
                o.z = fmaxf(s.z+dd.z+bb.z, 0.f);
                o.w = fmaxf(s.w+dd.w+bb.w, 0.f);
                ((float4*)dst)[k4] = o;
            }
        } else {
            #pragma unroll
            for (int k4 = 0; k4 < 6; k4++)
                ((float4*)dst)[k4] = make_float4(0.f,0.f,0.f,0.f);
        }
        __syncthreads();

        // ---- layer 1 ----
        float acc[6][4];
        #pragma unroll
        for (int nt = 0; nt < 6; nt++) {
            int c = nhalf*48 + nt*8 + cb;
            float bA = sb1[c], bB2 = sb1[c+1];
            acc[nt][0]=bA; acc[nt][1]=bB2; acc[nt][2]=bA; acc[nt][3]=bB2;
        }
        run_layer_tf32(pa0, pa1, pb1h, pb1l, acc);
        __syncthreads();
        // epilogue 1: relu -> fp32 back into A smem
        #pragma unroll
        for (int nt = 0; nt < 6; nt++) {
            int c = nhalf*48 + nt*8 + cb;
            float2 vlo = make_float2(fmaxf(acc[nt][0],0.f), fmaxf(acc[nt][1],0.f));
            float2 vhi = make_float2(fmaxf(acc[nt][2],0.f), fmaxf(acc[nt][3],0.f));
            *(float2*)(sA + r0*AST + c)     = vlo;
            *(float2*)(sA + (r0+8)*AST + c) = vhi;
        }
        __syncthreads();

        // ---- layer 2 ----
        #pragma unroll
        for (int nt = 0; nt < 6; nt++) {
            int c = nhalf*48 + nt*8 + cb;
            float bA = sb2[c], bB2 = sb2[c+1];
            acc[nt][0]=bA; acc[nt][1]=bB2; acc[nt][2]=bA; acc[nt][3]=bB2;
        }
        run_layer_tf32(pa0, pa1, pb2h, pb2l, acc);
        __syncthreads();
        // epilogue 2: relu -> stage (stride 97, aliases A), then per-node sum
        float* stg = sA;
        #pragma unroll
        for (int nt = 0; nt < 6; nt++) {
            int c = nhalf*48 + nt*8 + cb;
            stg[r0*97 + c]       = fmaxf(acc[nt][0], 0.f);
            stg[r0*97 + c + 1]   = fmaxf(acc[nt][1], 0.f);
            stg[(r0+8)*97 + c]   = fmaxf(acc[nt][2], 0.f);
            stg[(r0+8)*97 + c+1] = fmaxf(acc[nt][3], 0.f);
        }
        __syncthreads();
        for (int idx = tid; idx < 576; idx += 512) {
            int i = idx / 96, c = idx % 96;
            float s = 0.f;
            #pragma unroll
            for (int e = 0; e < 20; e++) s += stg[(i*20+e)*97 + c];
            g_m[(size_t)(g*6+i)*96 + c] = s;
        }
        __syncthreads();
    }
}

// ========================= LSTM pointwise + per-step logits (8 nodes/block) =========================
__global__ void __launch_bounds__(768) lstm_kernel(const float* __restrict__ outW,
                                                   const float* __restrict__ outb, int t)
{
    int slot = threadIdx.x / 96, j = threadIdx.x % 96;
    int n = blockIdx.x*8 + slot;
    __shared__ float sh[8][HD];
    size_t b4 = (size_t)n*384 + j;
    float gi = g_gx[b4      ] + g_gm[b4      ] + g_bc[j];
    float gf = g_gx[b4 +  96] + g_gm[b4 +  96] + g_bc[96+j];
    float gg = g_gx[b4 + 192] + g_gm[b4 + 192] + g_bc[192+j];
    float go = g_gx[b4 + 288] + g_gm[b4 + 288] + g_bc[288+j];
    if (t > 0) {
        const float* hw = g_S1 + (size_t)n*576 + 192 + j;
        gi += hw[0]; gf += hw[96]; gg += hw[192]; go += hw[288];
    }
    float si = 1.f/(1.f + expf(-gi));
    float sf = 1.f/(1.f + expf(-gf));
    float so = 1.f/(1.f + expf(-go));
    float cn = sf * g_c[(size_t)n*96 + j] + si * tanhf(gg);
    float hn = so * tanhf(cn);
    g_c[(size_t)n*96 + j] = cn;
    g_h[(size_t)n*96 + j] = hn;
    sh[slot][j] = hn;
    __syncthreads();
    if (j < 10) {
        float s = outb[j];
        const float* w = outW + j*96;
        #pragma unroll 8
        for (int k = 0; k < 96; k++) s = fmaf(sh[slot][k], w[k], s);
        g_logits[((size_t)t*NNODE + n)*10 + j] = s;
    }
}

// ========================= preds / loss / lf =========================
__global__ void finalize_kernel(const int* __restrict__ labels,
                                float* __restrict__ out, int out_size)
{
    int idx = blockIdx.x*blockDim.x + threadIdx.x;
    double term = 0.0;
    if (idx < TSTEPS*NNODE) {
        const float* l = g_logits + (size_t)idx*10;
        float mx = l[0]; int am = 0;
        #pragma unroll
        for (int d = 1; d < 10; d++) if (l[d] > mx) { mx = l[d]; am = d; }
        float se = 0.f;
        #pragma unroll
        for (int d = 0; d < 10; d++) se += expf(l[d] - mx);
        float lse = mx + logf(se);
        int lab = labels[idx % NNODE];
        term = (double)(lse - l[lab]);

        const int FULL = TSTEPS*NNODE*11 + 1;  // preds + loss + lf
        if (out_size >= FULL) {
            out[idx] = (float)am;
            float* lf = out + TSTEPS*NNODE + 1 + (size_t)idx*10;
            #pragma unroll
            for (int d = 0; d < 10; d++) lf[d] = l[d];
        } else {
            float* lf = out + (size_t)idx*10;
            #pragma unroll
            for (int d = 0; d < 10; d++) lf[d] = l[d];
        }
    }
    #pragma unroll
    for (int o = 16; o; o >>= 1)
        term += __shfl_down_sync(0xffffffffu, term, o);
    if ((threadIdx.x & 31) == 0 && term != 0.0) atomicAdd(&g_loss, term);
}

__global__ void loss_kernel(float* __restrict__ out, int out_size)
{
    const int FULL = TSTEPS*NNODE*11 + 1;
    if (out_size >= FULL)
        out[TSTEPS*NNODE] = (float)(g_loss / (double)(TSTEPS*NNODE));
}

// ========================= launch =========================
extern "C" void kernel_launch(void* const* d_in, const int* in_sizes, int n_in,
                              void* d_out, int out_size)
{
    const int*   q      = (const int*)  d_in[0];
    const int*   row    = (const int*)  d_in[1];
    const int*   col    = (const int*)  d_in[2];
    const int*   labels = (const int*)  d_in[3];
    const float* d_emb  = (const float*)d_in[6];
    const float* r_emb  = (const float*)d_in[7];
    const float* c_emb  = (const float*)d_in[8];
    const float* in_W0  = (const float*)d_in[9];
    const float* in_W   = (const float*)d_in[10];
    const float* in_b   = (const float*)d_in[11];
    const float* msg_W0 = (const float*)d_in[12];
    const float* msg_W  = (const float*)d_in[13];
    const float* msg_b  = (const float*)d_in[14];
    const float* W_ih   = (const float*)d_in[15];
    const float* W_hh   = (const float*)d_in[16];
    const float* out_W  = (const float*)d_in[17];
    const float* out_b  = (const float*)d_in[18];
    float* out = (float*)d_out;

    const int IN_SMEM = (48*96 + 3*9216 + 8*240) * 4;
    cudaFuncSetAttribute(input_kernel,   cudaFuncAttributeMaxDynamicSharedMemorySize, IN_SMEM);
    cudaFuncSetAttribute(edge_tc_kernel, cudaFuncAttributeMaxDynamicSharedMemorySize, EK_SMEM);

    float *px, *pS1, *pm, *pgx, *pgm, *ph, *pWpack, *pWcomb;
    cudaGetSymbolAddress((void**)&px,     g_x);
    cudaGetSymbolAddress((void**)&pS1,    g_S1);
    cudaGetSymbolAddress((void**)&pm,     g_m);
    cudaGetSymbolAddress((void**)&pgx,    g_gx);
    cudaGetSymbolAddress((void**)&pgm,    g_gm);
    cudaGetSymbolAddress((void**)&ph,     g_h);
    cudaGetSymbolAddress((void**)&pWpack, g_Wpack);
    cudaGetSymbolAddress((void**)&pWcomb, g_Wcomb);

    pack_kernel<<<192, 256>>>(msg_W, in_W, in_W0, msg_W0, W_hh, W_ih, msg_b);
    input_kernel<<<152, 768, IN_SMEM>>>(q, row, col, d_emb, r_emb, c_emb, in_b);
    // gx = x @ W_ih[:, :96]^T  (step-invariant)
    sgemm_awt<<<dim3(384/64, NNODE/64), 256>>>(px, W_ih, pgx, 384, 192, 0);

    for (int t = 0; t < TSTEPS; t++) {
        // S1 = h @ [W0a; W0b; W_hh]^T  -> [a_src | a_dst | hW]
        sgemm_awt<<<dim3(576/64, NNODE/64), 256>>>(ph, pWpack, pS1, 576, 96, 0);
        edge_tc_kernel<<<152, 512, EK_SMEM>>>(msg_b);
        // gm = Z @ (W_ihm @ W3)^T   (+bc added in lstm)
        sgemm_awt<<<dim3(384/64, NNODE/64), 256>>>(pm, pWcomb, pgm, 384, 96, 0);
        lstm_kernel<<<NNODE/8, 768>>>(out_W, out_b, t);
    }

    finalize_kernel<<<(TSTEPS*NNODE + 255)/256, 256>>>(labels, out, out_size);
    loss_kernel<<<1, 1>>>(out, out_size);
}

// round 6
// speedup vs baseline: 2.2948x; 1.0023x over previous
#include <cuda_runtime.h>
#include <cuda_bf16.h>
#include <math.h>
#include <stdint.h>

#define NB     128
#define NCELLS 81
#define NNODE  (NB*NCELLS)     // 10368
#define HD     96
#define TSTEPS 16
#define NTILES (NNODE/6)       // 1728 tiles of 6 nodes (120 edges + 8 pad)

// ========================= tf32 mma helpers (arch-agnostic, sm_80+) =========================
#define MMA1688(c,a0,a1,a2,a3,b0,b1) \
    asm volatile("mma.sync.aligned.m16n8k8.row.col.f32.tf32.tf32.f32 " \
        "{%0,%1,%2,%3}, {%4,%5,%6,%7}, {%8,%9}, {%0,%1,%2,%3};" \
        : "+f"((c)[0]),"+f"((c)[1]),"+f"((c)[2]),"+f"((c)[3]) \
        : "r"(a0),"r"(a1),"r"(a2),"r"(a3), "r"(b0),"r"(b1))

__device__ __forceinline__ uint32_t f2tf(float x) {
    uint32_t r; asm("cvt.rna.tf32.f32 %0, %1;" : "=r"(r) : "f"(x)); return r;
}
__device__ __forceinline__ float tf2f(uint32_t u) { return __uint_as_float(u); }

#define WST    104             // edge W image row stride (floats)
#define AST    100             // edge A row stride (floats)
#define WMATF  (96*104)

// ========================= device scratch =========================
__device__ float g_x[NNODE*HD];
__device__ float g_gx[NNODE*4*HD];
__device__ float g_S1[NNODE*6*HD];      // per-row: [a_src(96) | a_dst(96) | hW(384)]
__device__ float g_m[NNODE*HD];         // Z = sum of layer-2 activations over 20 edges
__device__ float g_gm[NNODE*4*HD];
__device__ float g_h[NNODE*HD];
__device__ float g_c[NNODE*HD];
__device__ float g_WTin[3*HD*HD];       // transposed in_W layers
__device__ float g_WTin0[48*HD];        // transposed in_W0
__device__ float g_bc[384];             // 20 * W_ihm @ b3
__device__ float g_Wsplit[4*WMATF];     // [W1hi | W1lo | W2hi | W2lo] k-major, stride 104
__device__ float g_WpackT[2*96*576];    // hi/lo k-major images of [W0a; W0b; W_hh]
__device__ float g_WcombT[2*96*384];    // hi/lo k-major images of (W_ihm @ W3)
__device__ float g_logits[(size_t)TSTEPS*NNODE*10];
__device__ double g_loss;

// ========================= weight packing =========================
__global__ void pack_kernel(const float* __restrict__ msg_W,
                            const float* __restrict__ in_W,
                            const float* __restrict__ in_W0,
                            const float* __restrict__ msg_W0,
                            const float* __restrict__ W_hh,
                            const float* __restrict__ W_ih,
                            const float* __restrict__ msg_b)
{
    int i = blockIdx.x*blockDim.x + threadIdx.x;
    int stride = gridDim.x*blockDim.x;
    for (int idx = i; idx < 3*HD*HD; idx += stride) {
        int l = idx / (HD*HD), r = idx % (HD*HD);
        int k = r / HD, j = r % HD;
        g_WTin[idx]  = in_W [l*HD*HD + j*HD + k];
    }
    for (int idx = i; idx < 48*HD; idx += stride) {
        int k = idx / HD, j = idx % HD;
        g_WTin0[idx] = in_W0[j*48 + k];
    }
    // Wpack hi/lo k-major: [576 o][96 k] source -> images [k][o]
    for (int idx = i; idx < 576*HD; idx += stride) {
        int o = idx / HD, k = idx % HD;
        float v;
        if (o < 96)       v = msg_W0[o*192 + k];            // W0a (src half)
        else if (o < 192) v = msg_W0[(o-96)*192 + 96 + k];  // W0b (dst half)
        else              v = W_hh[(o-192)*HD + k];
        float hi = tf2f(f2tf(v));
        g_WpackT[k*576 + o]            = hi;
        g_WpackT[96*576 + k*576 + o]   = tf2f(f2tf(v - hi));
    }
    // k-major tf32 hi/lo images of msg layers 1,2: WT[k][j], stride 104
    for (int idx = i; idx < 4*WMATF; idx += stride) {
        int part = idx / WMATF;             // 0=W1hi 1=W1lo 2=W2hi 3=W2lo
        int r2 = idx % WMATF;
        int k = r2 / WST, j = r2 % WST;
        int layer = part >> 1, which = part & 1;
        float w = (j < 96) ? msg_W[layer*HD*HD + j*HD + k] : 0.f;
        float hi = tf2f(f2tf(w));
        g_Wsplit[idx] = which ? tf2f(f2tf(w - hi)) : hi;
    }
    // Wcomb[o][k] = sum_c W_ihm[o][c] * W3[c][k] -> hi/lo k-major images
    for (int idx = i; idx < 384*HD; idx += stride) {
        int o = idx/HD, k = idx%HD;
        float s = 0.f;
        const float* wm = W_ih + o*192 + 96;
        const float* w3 = msg_W + 2*HD*HD + k;
        #pragma unroll 8
        for (int c = 0; c < 96; c++) s = fmaf(wm[c], w3[c*96], s);
        float hi = tf2f(f2tf(s));
        g_WcombT[k*384 + o]            = hi;
        g_WcombT[96*384 + k*384 + o]   = tf2f(f2tf(s - hi));
    }
    for (int idx = i; idx < 384; idx += stride) {
        float s = 0.f;
        #pragma unroll 8
        for (int c = 0; c < 96; c++) s = fmaf(W_ih[idx*192+96+c], msg_b[288+c], s);
        g_bc[idx] = 20.f * s;
    }
    if (i == 0) g_loss = 0.0;
}

// ========================= fp32 sgemm (used once for gx) =========================
__global__ void __launch_bounds__(256) sgemm_awt(const float* __restrict__ A,
                                                 const float* __restrict__ W,
                                                 float* __restrict__ C,
                                                 int Nc, int ldw, int woff)
{
    __shared__ float As[16][68];
    __shared__ float Ws[16][68];
    int bm = blockIdx.y * 64, bn = blockIdx.x * 64;
    int tid = threadIdx.x;
    int tx = tid & 15, ty = tid >> 4;
    int lr = tid >> 2, lk = (tid & 3) << 2;
    float acc[4][4];
    #pragma unroll
    for (int i = 0; i < 4; i++)
        #pragma unroll
        for (int j = 0; j < 4; j++) acc[i][j] = 0.f;

    for (int k0 = 0; k0 < 96; k0 += 16) {
        float4 a = *(const float4*)(A + (size_t)(bm+lr)*96 + k0 + lk);
        As[lk+0][lr]=a.x; As[lk+1][lr]=a.y; As[lk+2][lr]=a.z; As[lk+3][lr]=a.w;
        float4 w = *(const float4*)(W + (size_t)(bn+lr)*ldw + woff + k0 + lk);
        Ws[lk+0][lr]=w.x; Ws[lk+1][lr]=w.y; Ws[lk+2][lr]=w.z; Ws[lk+3][lr]=w.w;
        __syncthreads();
        #pragma unroll
        for (int k = 0; k < 16; k++) {
            float4 a4 = *(const float4*)&As[k][ty*4];
            float4 w4 = *(const float4*)&Ws[k][tx*4];
            float av[4] = {a4.x, a4.y, a4.z, a4.w};
            float wv[4] = {w4.x, w4.y, w4.z, w4.w};
            #pragma unroll
            for (int i = 0; i < 4; i++)
                #pragma unroll
                for (int j = 0; j < 4; j++)
                    acc[i][j] = fmaf(av[i], wv[j], acc[i][j]);
        }
        __syncthreads();
    }
    #pragma unroll
    for (int i = 0; i < 4; i++) {
        float4 o = make_float4(acc[i][0], acc[i][1], acc[i][2], acc[i][3]);
        *(float4*)(C + (size_t)(bm + ty*4 + i)*Nc + bn + tx*4) = o;
    }
}

// ========================= tf32 GEMM: C = A @ W^T (pre-split k-major W images) =========================
// A [M,96] fp32 row-major; WT = [2][96][Nc] hi/lo; C [M,Nc]. Tile 64x64, 256 thr.
#define GAST 100
#define GWST 72
#define GEMM_SMEM ((64*GAST + 2*96*GWST) * 4)   // 25600 + 55296 = 80896 B

__global__ void __launch_bounds__(256) gemm_tf32(const float* __restrict__ A,
                                                 const float* __restrict__ WT,
                                                 float* __restrict__ C, int Nc)
{
    extern __shared__ float sg[];
    float* sA = sg;                    // 64 x GAST
    float* sW = sg + 64*GAST;          // 2 x 96 x GWST
    int bm = blockIdx.y*64, bn = blockIdx.x*64;
    int tid = threadIdx.x, lane = tid & 31, wid = tid >> 5;

    for (int i = tid; i < 64*24; i += 256) {
        int r = i / 24, c4 = (i % 24) * 4;
        float4 v = *(const float4*)(A + (size_t)(bm+r)*96 + c4);
        float* d = sA + r*GAST + c4;
        d[0]=v.x; d[1]=v.y; d[2]=v.z; d[3]=v.w;
    }
    for (int i = tid; i < 2*96*16; i += 256) {
        int part = i / (96*16);
        int r2 = i % (96*16);
        int k = r2 / 16, c4 = (r2 % 16) * 4;
        float4 v = *(const float4*)(WT + (size_t)part*96*Nc + (size_t)k*Nc + bn + c4);
        float* d = sW + part*96*GWST + k*GWST + c4;
        d[0]=v.x; d[1]=v.y; d[2]=v.z; d[3]=v.w;
    }
    __syncthreads();

    int mtile = wid >> 1, nhalf = wid & 1;
    const float* pa0 = sA + (mtile*16 + (lane>>2))*GAST + (lane&3);
    const float* pa1 = pa0 + 8*GAST;
    int foff = (lane&3)*GWST + (lane>>2) + nhalf*32;
    const float* pbh = sW + foff;
    const float* pbl = sW + 96*GWST + foff;

    float acc[4][4];
    #pragma unroll
    for (int nt = 0; nt < 4; nt++)
        #pragma unroll
        for (int j = 0; j < 4; j++) acc[nt][j] = 0.f;

    #pragma unroll 1
    for (int kt = 0; kt < 12; kt++) {
        float va0 = pa0[kt*8],   va2 = pa0[kt*8+4];
        float va1 = pa1[kt*8],   va3 = pa1[kt*8+4];
        uint32_t ah0=f2tf(va0), ah1=f2tf(va1), ah2=f2tf(va2), ah3=f2tf(va3);
        uint32_t al0=f2tf(va0-tf2f(ah0)), al1=f2tf(va1-tf2f(ah1));
        uint32_t al2=f2tf(va2-tf2f(ah2)), al3=f2tf(va3-tf2f(ah3));
        const float* ph = pbh + kt*8*GWST;
        const float* pl = pbl + kt*8*GWST;
        #pragma unroll
        for (int nt = 0; nt < 4; nt++) {
            uint32_t bh0 = __float_as_uint(ph[nt*8]);
            uint32_t bh1 = __float_as_uint(ph[nt*8 + 4*GWST]);
            uint32_t bl0 = __float_as_uint(pl[nt*8]);
            uint32_t bl1 = __float_as_uint(pl[nt*8 + 4*GWST]);
            MMA1688(acc[nt], ah0,ah1,ah2,ah3, bh0,bh1);
            MMA1688(acc[nt], al0,al1,al2,al3, bh0,bh1);
            MMA1688(acc[nt], ah0,ah1,ah2,ah3, bl0,bl1);
        }
    }

    int cb = (lane & 3) * 2;
    int r0 = mtile*16 + (lane >> 2);
    #pragma unroll
    for (int nt = 0; nt < 4; nt++) {
        int c = bn + nhalf*32 + nt*8 + cb;
        *(float2*)(C + (size_t)(bm+r0)*Nc + c)   = make_float2(acc[nt][0], acc[nt][1]);
        *(float2*)(C + (size_t)(bm+r0+8)*Nc + c) = make_float2(acc[nt][2], acc[nt][3]);
    }
}

// ========================= input embedding + MLP =========================
__device__ __forceinline__ float dot96(const float* __restrict__ WTcol,
                                       const float* __restrict__ vin)
{
    float s = 0.f;
    #pragma unroll 8
    for (int k4 = 0; k4 < 24; k4++) {
        float4 a = ((const float4*)vin)[k4];
        s = fmaf(WTcol[(4*k4+0)*96], a.x, s);
        s = fmaf(WTcol[(4*k4+1)*96], a.y, s);
        s = fmaf(WTcol[(4*k4+2)*96], a.z, s);
        s = fmaf(WTcol[(4*k4+3)*96], a.w, s);
    }
    return s;
}

__global__ void __launch_bounds__(768) input_kernel(const int* __restrict__ q,
    const int* __restrict__ rw, const int* __restrict__ cl,
    const float* __restrict__ demb, const float* __restrict__ remb,
    const float* __restrict__ cemb, const float* __restrict__ inb)
{
    extern __shared__ float sm[];
    float* sW0 = sm;
    float* sWT = sm + 48*96;
    float* svb = sWT + 3*9216;
    for (int i = threadIdx.x; i < 48*96;  i += 768) sW0[i] = g_WTin0[i];
    for (int i = threadIdx.x; i < 3*9216; i += 768) sWT[i] = g_WTin[i];
    __syncthreads();

    int slot = threadIdx.x / 96, j = threadIdx.x % 96;
    float* v0 = svb + slot*240;
    float* vA = v0 + 48;
    float* vB = vA + 96;
    int sg = blockIdx.x*8 + slot;
    int stride = gridDim.x*8;
    int iters = (NNODE + stride - 1) / stride;
    float b0 = inb[j], b1 = inb[96+j], b2 = inb[192+j], b3 = inb[288+j];

    for (int it = 0; it < iters; it++) {
        int node = sg + it*stride;
        bool act = node < NNODE;
        int n = act ? node : NNODE-1;
        if (j < 16)      v0[j] = demb[q[n]*16 + j];
        else if (j < 32) v0[j] = remb[rw[n]*16 + (j-16)];
        else if (j < 48) v0[j] = cemb[cl[n]*16 + (j-32)];
        __syncthreads();
        float s = b0;
        #pragma unroll
        for (int k4 = 0; k4 < 12; k4++) {
            float4 a = ((const float4*)v0)[k4];
            s = fmaf(sW0[(4*k4+0)*96+j], a.x, s);
            s = fmaf(sW0[(4*k4+1)*96+j], a.y, s);
            s = fmaf(sW0[(4*k4+2)*96+j], a.z, s);
            s = fmaf(sW0[(4*k4+3)*96+j], a.w, s);
        }
        vA[j] = fmaxf(s, 0.f);
        __syncthreads();
        float t1 = b1 + dot96(sWT + j, vA);
        vB[j] = fmaxf(t1, 0.f);
        __syncthreads();
        float t2 = b2 + dot96(sWT + 9216 + j, vB);
        vA[j] = fmaxf(t2, 0.f);
        __syncthreads();
        float t3 = b3 + dot96(sWT + 2*9216 + j, vA);
        if (act) {
            g_x[(size_t)node*96 + j] = t3;
            g_h[(size_t)node*96 + j] = t3;   // h0 = x
            g_c[(size_t)node*96 + j] = 0.f;  // c0 = 0
        }
        __syncthreads();
    }
}

// ========================= tf32 HMMA edge pipeline =========================
// smem (bytes):
#define OFF_B0     0               // 96 floats
#define OFF_B1     384
#define OFF_B2     768
#define OFF_NBR    1152            // 81*20 ints -> ends 7632
#define OFF_W      7680            // 4 x (96 x 104) floats = 159,744 B
#define OFF_A      167424          // 128 x 100 floats = 51,200 B
#define EK_SMEM    218624

#define BAR_PAIR(m) asm volatile("bar.sync %0, %1;" :: "r"(1+(m)), "r"(64) : "memory")

// one layer via 3xTF32 (weights pre-split): acc[6][4] += A @ W^T (this warp's n48 half)
__device__ __forceinline__ void run_layer_tf32(const float* __restrict__ pa0,
                                               const float* __restrict__ pa1,
                                               const float* __restrict__ pbh,
                                               const float* __restrict__ pbl,
                                               float acc[6][4])
{
    #pragma unroll 1
    for (int kt = 0; kt < 12; kt++) {
        float va0 = pa0[kt*8],   va2 = pa0[kt*8+4];
        float va1 = pa1[kt*8],   va3 = pa1[kt*8+4];
        uint32_t ah0=f2tf(va0), ah1=f2tf(va1), ah2=f2tf(va2), ah3=f2tf(va3);
        uint32_t al0=f2tf(va0-tf2f(ah0)), al1=f2tf(va1-tf2f(ah1));
        uint32_t al2=f2tf(va2-tf2f(ah2)), al3=f2tf(va3-tf2f(ah3));
        const float* ph = pbh + kt*8*WST;
        const float* pl = pbl + kt*8*WST;
        #pragma unroll
        for (int nt = 0; nt < 6; nt++) {
            uint32_t bh0 = __float_as_uint(ph[nt*8]);
            uint32_t bh1 = __float_as_uint(ph[nt*8 + 4*WST]);
            uint32_t bl0 = __float_as_uint(pl[nt*8]);
            uint32_t bl1 = __float_as_uint(pl[nt*8 + 4*WST]);
            MMA1688(acc[nt], ah0,ah1,ah2,ah3, bh0,bh1);
            MMA1688(acc[nt], al0,al1,al2,al3, bh0,bh1);
            MMA1688(acc[nt], ah0,ah1,ah2,ah3, bl0,bl1);
        }
    }
}

__global__ void __launch_bounds__(512) edge_tc_kernel(const float* __restrict__ msgb)
{
    extern __shared__ char smc[];
    float* sb0 = (float*)(smc + OFF_B0);
    float* sb1 = (float*)(smc + OFF_B1);
    float* sb2 = (float*)(smc + OFF_B2);
    int*  snbr = (int*)(smc + OFF_NBR);
    float* sW  = (float*)(smc + OFF_W);
    float* sA  = (float*)(smc + OFF_A);
    int tid = threadIdx.x, lane = tid & 31, wid = tid >> 5;

    if (tid < 96) { sb0[tid]=msgb[tid]; sb1[tid]=msgb[96+tid]; sb2[tid]=msgb[192+tid]; }
    if (tid < 81) {
        int u = tid;
        int ru = u/9, cu = u%9, bu = (ru/3)*3 + cu/3;
        int cnt = 0;
        for (int v = 0; v < 81; v++) {
            if (v == u) continue;
            int rv = v/9, cv = v%9, bv = (rv/3)*3 + cv/3;
            if (rv == ru || cv == cu || bv == bu) snbr[u*20 + cnt++] = v;
        }
    }
    for (int i = tid; i < 4*WMATF/4; i += 512)
        ((float4*)sW)[i] = ((const float4*)g_Wsplit)[i];
    __syncthreads();

    // fragment pointers: warp = (mtile, nhalf)
    int mtile = wid >> 1, nhalf = wid & 1;
    const float* pa0 = sA + (mtile*16 + (lane>>2))*AST + (lane&3);
    const float* pa1 = pa0 + 8*AST;
    int foff = (lane&3)*WST + (lane>>2) + nhalf*48;
    const float* pb1h = sW + 0*WMATF + foff;
    const float* pb1l = sW + 1*WMATF + foff;
    const float* pb2h = sW + 2*WMATF + foff;
    const float* pb2l = sW + 3*WMATF + foff;
    int cb = (lane & 3) * 2;
    int r0 = mtile*16 + (lane >> 2);
    int rA = tid & 127, part = tid >> 7;   // A-build: row, col-quarter (24 cols)

    for (int g = blockIdx.x; g < NTILES; g += gridDim.x) {
        // ---- build E0 = relu(a_src + a_dst + b0) as fp32 into A smem ----
        float* dst = sA + rA*AST + part*24;
        if (rA < 120) {
            int dnode = g*6 + rA/20;
            int cell = dnode % 81;
            int srcn = dnode - cell + snbr[cell*20 + (rA % 20)];
            const float4* aS = (const float4*)(g_S1 + (size_t)srcn*576 + part*24);
            const float4* aD = (const float4*)(g_S1 + (size_t)dnode*576 + 96 + part*24);
            const float4* bB = (const float4*)(sb0 + part*24);
            #pragma unroll
            for (int k4 = 0; k4 < 6; k4++) {
                float4 s = aS[k4], dd = aD[k4], bb = bB[k4];
                float4 o;
                o.x = fmaxf(s.x+dd.x+bb.x, 0.f);
                o.y = fmaxf(s.y+dd.y+bb.y, 0.f);
                o.z = fmaxf(s.z+dd.z+bb.z, 0.f);
                o.w = fmaxf(s.w+dd.w+bb.w, 0.f);
                ((float4*)dst)[k4] = o;
            }
        } else {
            #pragma unroll
            for (int k4 = 0; k4 < 6; k4++)
                ((float4*)dst)[k4] = make_float4(0.f,0.f,0.f,0.f);
        }
        __syncthreads();

        // ---- layer 1 ----
        float acc[6][4];
        #pragma unroll
        for (int nt = 0; nt < 6; nt++) {
            int c = nhalf*48 + nt*8 + cb;
            float bA = sb1[c], bB2 = sb1[c+1];
            acc[nt][0]=bA; acc[nt][1]=bB2; acc[nt][2]=bA; acc[nt][3]=bB2;
        }
        run_layer_tf32(pa0, pa1, pb1h, pb1l, acc);
        BAR_PAIR(mtile);   // only pair (mtile,0/1) shares these A rows
        // epilogue 1: relu -> fp32 back into A smem (own mtile rows)
        #pragma unroll
        for (int nt = 0; nt < 6; nt++) {
            int c = nhalf*48 + nt*8 + cb;
            float2 vlo = make_float2(fmaxf(acc[nt][0],0.f), fmaxf(acc[nt][1],0.f));
            float2 vhi = make_float2(fmaxf(acc[nt][2],0.f), fmaxf(acc[nt][3],0.f));
            *(float2*)(sA + r0*AST + c)     = vlo;
            *(float2*)(sA + (r0+8)*AST + c) = vhi;
        }
        BAR_PAIR(mtile);

        // ---- layer 2 ----
        #pragma unroll
        for (int nt = 0; nt < 6; nt++) {
            int c = nhalf*48 + nt*8 + cb;
            float bA = sb2[c], bB2 = sb2[c+1];
            acc[nt][0]=bA; acc[nt][1]=bB2; acc[nt][2]=bA; acc[nt][3]=bB2;
        }
        run_layer_tf32(pa0, pa1, pb2h, pb2l, acc);
        BAR_PAIR(mtile);
        // epilogue 2: relu -> stage (stride AST, aliases A rows of own mtile)
        float* stg = sA;
        #pragma unroll
        for (int nt = 0; nt < 6; nt++) {
            int c = nhalf*48 + nt*8 + cb;
            stg[r0*AST + c]       = fmaxf(acc[nt][0], 0.f);
            stg[r0*AST + c + 1]   = fmaxf(acc[nt][1], 0.f);
            stg[(r0+8)*AST + c]   = fmaxf(acc[nt][2], 0.f);
            stg[(r0+8)*AST + c+1] = fmaxf(acc[nt][3], 0.f);
        }
        __syncthreads();   // full: sum reads all rows
        for (int idx = tid; idx < 576; idx += 512) {
            int i = idx / 96, c = idx % 96;
            float s = 0.f;
            #pragma unroll
            for (int e = 0; e < 20; e++) s += stg[(i*20+e)*AST + c];
            g_m[(size_t)(g*6+i)*96 + c] = s;
        }
        __syncthreads();   // full: next build overwrites A
    }
}

// ========================= LSTM pointwise + per-step logits (8 nodes/block) =========================
__global__ void __launch_bounds__(768) lstm_kernel(const float* __restrict__ outW,
                                                   const float* __restrict__ outb, int t)
{
    int slot = threadIdx.x / 96, j = threadIdx.x % 96;
    int n = blockIdx.x*8 + slot;
    __shared__ float sh[8][HD];
    size_t b4 = (size_t)n*384 + j;
    float gi = g_gx[b4      ] + g_gm[b4      ] + g_bc[j];
    float gf = g_gx[b4 +  96] + g_gm[b4 +  96] + g_bc[96+j];
    float gg = g_gx[b4 + 192] + g_gm[b4 + 192] + g_bc[192+j];
    float go = g_gx[b4 + 288] + g_gm[b4 + 288] + g_bc[288+j];
    if (t > 0) {
        const float* hw = g_S1 + (size_t)n*576 + 192 + j;
        gi += hw[0]; gf += hw[96]; gg += hw[192]; go += hw[288];
    }
    float si = 1.f/(1.f + expf(-gi));
    float sf = 1.f/(1.f + expf(-gf));
    float so = 1.f/(1.f + expf(-go));
    float cn = sf * g_c[(size_t)n*96 + j] + si * tanhf(gg);
    float hn = so * tanhf(cn);
    g_c[(size_t)n*96 + j] = cn;
    g_h[(size_t)n*96 + j] = hn;
    sh[slot][j] = hn;
    __syncthreads();
    if (j < 10) {
        float s = outb[j];
        const float* w = outW + j*96;
        #pragma unroll 8
        for (int k = 0; k < 96; k++) s = fmaf(sh[slot][k], w[k], s);
        g_logits[((size_t)t*NNODE + n)*10 + j] = s;
    }
}

// ========================= preds / loss / lf =========================
__global__ void finalize_kernel(const int* __restrict__ labels,
                                float* __restrict__ out, int out_size)
{
    int idx = blockIdx.x*blockDim.x + threadIdx.x;
    double term = 0.0;
    if (idx < TSTEPS*NNODE) {
        const float* l = g_logits + (size_t)idx*10;
        float mx = l[0]; int am = 0;
        #pragma unroll
        for (int d = 1; d < 10; d++) if (l[d] > mx) { mx = l[d]; am = d; }
        float se = 0.f;
        #pragma unroll
        for (int d = 0; d < 10; d++) se += expf(l[d] - mx);
        float lse = mx + logf(se);
        int lab = labels[idx % NNODE];
        term = (double)(lse - l[lab]);

        const int FULL = TSTEPS*NNODE*11 + 1;  // preds + loss + lf
        if (out_size >= FULL) {
            out[idx] = (float)am;
            float* lf = out + TSTEPS*NNODE + 1 + (size_t)idx*10;
            #pragma unroll
            for (int d = 0; d < 10; d++) lf[d] = l[d];
        } else {
            float* lf = out + (size_t)idx*10;
            #pragma unroll
            for (int d = 0; d < 10; d++) lf[d] = l[d];
        }
    }
    #pragma unroll
    for (int o = 16; o; o >>= 1)
        term += __shfl_down_sync(0xffffffffu, term, o);
    if ((threadIdx.x & 31) == 0 && term != 0.0) atomicAdd(&g_loss, term);
}

__global__ void loss_kernel(float* __restrict__ out, int out_size)
{
    const int FULL = TSTEPS*NNODE*11 + 1;
    if (out_size >= FULL)
        out[TSTEPS*NNODE] = (float)(g_loss / (double)(TSTEPS*NNODE));
}

// ========================= launch =========================
extern "C" void kernel_launch(void* const* d_in, const int* in_sizes, int n_in,
                              void* d_out, int out_size)
{
    const int*   q      = (const int*)  d_in[0];
    const int*   row    = (const int*)  d_in[1];
    const int*   col    = (const int*)  d_in[2];
    const int*   labels = (const int*)  d_in[3];
    const float* d_emb  = (const float*)d_in[6];
    const float* r_emb  = (const float*)d_in[7];
    const float* c_emb  = (const float*)d_in[8];
    const float* in_W0  = (const float*)d_in[9];
    const float* in_W   = (const float*)d_in[10];
    const float* in_b   = (const float*)d_in[11];
    const float* msg_W0 = (const float*)d_in[12];
    const float* msg_W  = (const float*)d_in[13];
    const float* msg_b  = (const float*)d_in[14];
    const float* W_ih   = (const float*)d_in[15];
    const float* W_hh   = (const float*)d_in[16];
    const float* out_W  = (const float*)d_in[17];
    const float* out_b  = (const float*)d_in[18];
    float* out = (float*)d_out;

    const int IN_SMEM = (48*96 + 3*9216 + 8*240) * 4;
    cudaFuncSetAttribute(input_kernel,   cudaFuncAttributeMaxDynamicSharedMemorySize, IN_SMEM);
    cudaFuncSetAttribute(edge_tc_kernel, cudaFuncAttributeMaxDynamicSharedMemorySize, EK_SMEM);
    cudaFuncSetAttribute(gemm_tf32,      cudaFuncAttributeMaxDynamicSharedMemorySize, GEMM_SMEM);

    float *px, *pm, *pgx, *pgm, *ph, *pWpackT, *pWcombT;
    cudaGetSymbolAddress((void**)&px,      g_x);
    cudaGetSymbolAddress((void**)&pm,      g_m);
    cudaGetSymbolAddress((void**)&pgx,     g_gx);
    cudaGetSymbolAddress((void**)&pgm,     g_gm);
    cudaGetSymbolAddress((void**)&ph,      g_h);
    cudaGetSymbolAddress((void**)&pWpackT, g_WpackT);
    cudaGetSymbolAddress((void**)&pWcombT, g_WcombT);
    float *pS1;
    cudaGetSymbolAddress((void**)&pS1,     g_S1);

    pack_kernel<<<192, 256>>>(msg_W, in_W, in_W0, msg_W0, W_hh, W_ih, msg_b);
    input_kernel<<<152, 768, IN_SMEM>>>(q, row, col, d_emb, r_emb, c_emb, in_b);
    // gx = x @ W_ih[:, :96]^T  (step-invariant, once)
    sgemm_awt<<<dim3(384/64, NNODE/64), 256>>>(px, W_ih, pgx, 384, 192, 0);

    for (int t = 0; t < TSTEPS; t++) {
        // S1 = h @ [W0a; W0b; W_hh]^T  -> [a_src | a_dst | hW]
        gemm_tf32<<<dim3(576/64, NNODE/64), 256, GEMM_SMEM>>>(ph, pWpackT, pS1, 576);
        edge_tc_kernel<<<152, 512, EK_SMEM>>>(msg_b);
        // gm = Z @ (W_ihm @ W3)^T   (+bc added in lstm)
        gemm_tf32<<<dim3(384/64, NNODE/64), 256, GEMM_SMEM>>>(pm, pWcombT, pgm, 384);
        lstm_kernel<<<NNODE/8, 768>>>(out_W, out_b, t);
    }

    finalize_kernel<<<(TSTEPS*NNODE + 255)/256, 256>>>(labels, out, out_size);
    loss_kernel<<<1, 1>>>(out, out_size);
}

// round 7
// speedup vs baseline: 3.5523x; 1.5479x over previous
#include <cuda_runtime.h>
#include <cuda_fp16.h>
#include <math.h>
#include <stdint.h>

#define NB     128
#define NCELLS 81
#define NNODE  (NB*NCELLS)     // 10368
#define HD     96
#define TSTEPS 16
#define NTILES (NNODE/6)       // 1728 tiles of 6 nodes (120 edges + 8 pad)
#define CORR   (1.0f/2048.0f)

// ========================= fp16 mma/ldmatrix helpers (sm_80+) =========================
#define MMAF(c,a0,a1,a2,a3,b0,b1) \
    asm volatile("mma.sync.aligned.m16n8k16.row.col.f32.f16.f16.f32 " \
        "{%0,%1,%2,%3}, {%4,%5,%6,%7}, {%8,%9}, {%0,%1,%2,%3};" \
        : "+f"((c)[0]),"+f"((c)[1]),"+f"((c)[2]),"+f"((c)[3]) \
        : "r"(a0),"r"(a1),"r"(a2),"r"(a3), "r"(b0),"r"(b1))
#define LDSM4(r0,r1,r2,r3,addr) \
    asm volatile("ldmatrix.sync.aligned.m8n8.x4.shared.b16 {%0,%1,%2,%3}, [%4];" \
        : "=r"(r0),"=r"(r1),"=r"(r2),"=r"(r3) : "r"(addr))
#define LDSM4T(r0,r1,r2,r3,addr) \
    asm volatile("ldmatrix.sync.aligned.m8n8.x4.trans.shared.b16 {%0,%1,%2,%3}, [%4];" \
        : "=r"(r0),"=r"(r1),"=r"(r2),"=r"(r3) : "r"(addr))

__device__ __forceinline__ uint32_t smem_u32(const void* p) {
    uint32_t a;
    asm("{ .reg .u64 t; cvta.to.shared.u64 t, %1; cvt.u32.u64 %0, t; }" : "=r"(a) : "l"(p));
    return a;
}
__device__ __forceinline__ uint32_t pk2(float a, float b) {
    __half2 h = __floats2half2_rn(a, b);
    return *(uint32_t*)&h;
}

// ========================= device scratch =========================
__device__ float  g_x[NNODE*HD];
__device__ float  g_gx[NNODE*4*HD];
__device__ float  g_S1[NNODE*6*HD];      // [a_src(96) | a_dst(96) | hW(384)]
__device__ float  g_gm[NNODE*4*HD];
__device__ float  g_c[NNODE*HD];
__device__ float  g_WTin[3*HD*HD];
__device__ float  g_WTin0[48*HD];
__device__ float  g_bc[384];
__device__ __half g_hH[NNODE*104], g_hL[NNODE*104];     // h hi/lo images (stride 104)
__device__ __half g_ZH[NNODE*104], g_ZL[NNODE*104];     // Z hi/lo images
__device__ __half g_Wmsg[4*96*104];                     // [W1h|W1l|W2h|W2l] k-major s104
__device__ __half g_WpackTH[96*576], g_WpackTL[96*576]; // k-major images of Wpack
__device__ __half g_WcombTH[96*384], g_WcombTL[96*384]; // k-major images of Wcomb
__device__ float  g_logits[(size_t)TSTEPS*NNODE*10];
__device__ double g_loss;

// ========================= weight packing =========================
__global__ void pack_kernel(const float* __restrict__ msg_W,
                            const float* __restrict__ in_W,
                            const float* __restrict__ in_W0,
                            const float* __restrict__ msg_W0,
                            const float* __restrict__ W_hh,
                            const float* __restrict__ W_ih,
                            const float* __restrict__ msg_b)
{
    int i = blockIdx.x*blockDim.x + threadIdx.x;
    int stride = gridDim.x*blockDim.x;
    for (int idx = i; idx < 3*HD*HD; idx += stride) {
        int l = idx / (HD*HD), r = idx % (HD*HD);
        int k = r / HD, j = r % HD;
        g_WTin[idx] = in_W[l*HD*HD + j*HD + k];
    }
    for (int idx = i; idx < 48*HD; idx += stride) {
        int k = idx / HD, j = idx % HD;
        g_WTin0[idx] = in_W0[j*48 + k];
    }
    // msg W1/W2 hi/lo fp16 images, k-major stride 104
    for (int idx = i; idx < 4*96*104; idx += stride) {
        int part = idx / (96*104);
        int r2 = idx % (96*104);
        int k = r2 / 104, j = r2 % 104;
        int layer = part >> 1, which = part & 1;
        float w = (j < 96) ? msg_W[layer*HD*HD + j*HD + k] : 0.f;
        __half hh = __float2half_rn(w);
        g_Wmsg[idx] = which ? __float2half_rn((w - __half2float(hh))*2048.f) : hh;
    }
    // Wpack = [W0a; W0b; W_hh] (576x96) -> hi/lo k-major [96][576]
    for (int idx = i; idx < 96*576; idx += stride) {
        int k = idx / 576, o = idx % 576;
        float v;
        if (o < 96)       v = msg_W0[o*192 + k];
        else if (o < 192) v = msg_W0[(o-96)*192 + 96 + k];
        else              v = W_hh[(o-192)*HD + k];
        __half hh = __float2half_rn(v);
        g_WpackTH[idx] = hh;
        g_WpackTL[idx] = __float2half_rn((v - __half2float(hh))*2048.f);
    }
    // Wcomb[o][k] = sum_c W_ihm[o][c]*W3[c][k] -> hi/lo k-major [96][384]
    for (int idx = i; idx < 96*384; idx += stride) {
        int k = idx / 384, o = idx % 384;
        float s = 0.f;
        const float* wm = W_ih + o*192 + 96;
        const float* w3 = msg_W + 2*HD*HD + k;
        #pragma unroll 8
        for (int c = 0; c < 96; c++) s = fmaf(wm[c], w3[c*96], s);
        __half hh = __float2half_rn(s);
        g_WcombTH[idx] = hh;
        g_WcombTL[idx] = __float2half_rn((s - __half2float(hh))*2048.f);
    }
    for (int idx = i; idx < 384; idx += stride) {
        float s = 0.f;
        #pragma unroll 8
        for (int c = 0; c < 96; c++) s = fmaf(W_ih[idx*192+96+c], msg_b[288+c], s);
        g_bc[idx] = 20.f * s;
    }
    if (i == 0) g_loss = 0.0;
}

// ========================= fp32 sgemm (gx, once) =========================
__global__ void __launch_bounds__(256) sgemm_awt(const float* __restrict__ A,
                                                 const float* __restrict__ W,
                                                 float* __restrict__ C,
                                                 int Nc, int ldw, int woff)
{
    __shared__ float As[16][68];
    __shared__ float Ws[16][68];
    int bm = blockIdx.y * 64, bn = blockIdx.x * 64;
    int tid = threadIdx.x;
    int tx = tid & 15, ty = tid >> 4;
    int lr = tid >> 2, lk = (tid & 3) << 2;
    float acc[4][4];
    #pragma unroll
    for (int i = 0; i < 4; i++)
        #pragma unroll
        for (int j = 0; j < 4; j++) acc[i][j] = 0.f;

    for (int k0 = 0; k0 < 96; k0 += 16) {
        float4 a = *(const float4*)(A + (size_t)(bm+lr)*96 + k0 + lk);
        As[lk+0][lr]=a.x; As[lk+1][lr]=a.y; As[lk+2][lr]=a.z; As[lk+3][lr]=a.w;
        float4 w = *(const float4*)(W + (size_t)(bn+lr)*ldw + woff + k0 + lk);
        Ws[lk+0][lr]=w.x; Ws[lk+1][lr]=w.y; Ws[lk+2][lr]=w.z; Ws[lk+3][lr]=w.w;
        __syncthreads();
        #pragma unroll
        for (int k = 0; k < 16; k++) {
            float4 a4 = *(const float4*)&As[k][ty*4];
            float4 w4 = *(const float4*)&Ws[k][tx*4];
            float av[4] = {a4.x, a4.y, a4.z, a4.w};
            float wv[4] = {w4.x, w4.y, w4.z, w4.w};
            #pragma unroll
            for (int i = 0; i < 4; i++)
                #pragma unroll
                for (int j = 0; j < 4; j++)
                    acc[i][j] = fmaf(av[i], wv[j], acc[i][j]);
        }
        __syncthreads();
    }
    #pragma unroll
    for (int i = 0; i < 4; i++) {
        float4 o = make_float4(acc[i][0], acc[i][1], acc[i][2], acc[i][3]);
        *(float4*)(C + (size_t)(bm + ty*4 + i)*Nc + bn + tx*4) = o;
    }
}

// ========================= fp16 3-term GEMM: C = A @ W^T =========================
// A images hi/lo [M rows, stride 104]; B images hi/lo k-major [96][Nc]; C fp32 [M][Nc]
#define GEMM_SMEM (2*64*104*2 + 2*96*72*2)   // 26624 + 27648 = 54272

__global__ void __launch_bounds__(256) gemm_f16(const __half* __restrict__ AH,
                                                const __half* __restrict__ AL,
                                                const __half* __restrict__ BH,
                                                const __half* __restrict__ BL,
                                                float* __restrict__ C, int Nc)
{
    extern __shared__ char sg[];
    __half* sA = (__half*)sg;             // hi 64x104 then lo 64x104
    __half* sB = (__half*)(sg + 2*64*104*2); // hi 96x72 then lo 96x72
    int bm = blockIdx.y*64, bn = blockIdx.x*64;
    int tid = threadIdx.x, lane = tid & 31, wid = tid >> 5;

    {   // A rows are contiguous (stride==104): bulk copy
        const uint4* gh = (const uint4*)(AH + (size_t)bm*104);
        const uint4* gl = (const uint4*)(AL + (size_t)bm*104);
        uint4* dh = (uint4*)sA;
        uint4* dl = (uint4*)(sA + 64*104);
        for (int i = tid; i < 832; i += 256) { dh[i] = gh[i]; dl[i] = gl[i]; }
        for (int i = tid; i < 2*96*8; i += 256) {
            int part = i / 768, r2 = i % 768;
            int k = r2 >> 3, c8 = (r2 & 7) * 8;
            const __half* src = (part ? BL : BH) + (size_t)k*Nc + bn + c8;
            *(uint4*)(sB + part*96*72 + k*72 + c8) = *(const uint4*)src;
        }
    }
    __syncthreads();

    int mtile = wid >> 1, nhalf = wid & 1;
    uint32_t aHb = smem_u32(sA) + (uint32_t)(((mtile*16 + (lane&15))*104 + ((lane>>4)<<3))*2);
    uint32_t aLb = aHb + 64*104*2;
    uint32_t bHb = smem_u32(sB) + (uint32_t)((((lane&15))*72 + nhalf*32 + ((lane>>4)<<3))*2);
    uint32_t bLb = bHb + 96*72*2;

    float am[4][4], ac[4][4];
    #pragma unroll
    for (int nt = 0; nt < 4; nt++)
        #pragma unroll
        for (int j = 0; j < 4; j++) { am[nt][j] = 0.f; ac[nt][j] = 0.f; }

    #pragma unroll
    for (int kt = 0; kt < 6; kt++) {
        uint32_t A0,A1,A2,A3, L0,L1,L2,L3;
        LDSM4(A0,A1,A2,A3, aHb + kt*32);
        LDSM4(L0,L1,L2,L3, aLb + kt*32);
        #pragma unroll
        for (int ntp = 0; ntp < 2; ntp++) {
            uint32_t h0,h1,h2,h3, l0,l1,l2,l3;
            LDSM4T(h0,h1,h2,h3, bHb + kt*2304 + ntp*32);
            LDSM4T(l0,l1,l2,l3, bLb + kt*2304 + ntp*32);
            MMAF(am[2*ntp  ], A0,A1,A2,A3, h0,h1);
            MMAF(ac[2*ntp  ], L0,L1,L2,L3, h0,h1);
            MMAF(ac[2*ntp  ], A0,A1,A2,A3, l0,l1);
            MMAF(am[2*ntp+1], A0,A1,A2,A3, h2,h3);
            MMAF(ac[2*ntp+1], L0,L1,L2,L3, h2,h3);
            MMAF(ac[2*ntp+1], A0,A1,A2,A3, l2,l3);
        }
    }

    int r0 = mtile*16 + (lane >> 2);
    int cb = (lane & 3) * 2;
    #pragma unroll
    for (int nt = 0; nt < 4; nt++) {
        int c = bn + nhalf*32 + nt*8 + cb;
        *(float2*)(C + (size_t)(bm+r0)*Nc + c) =
            make_float2(am[nt][0] + ac[nt][0]*CORR, am[nt][1] + ac[nt][1]*CORR);
        *(float2*)(C + (size_t)(bm+r0+8)*Nc + c) =
            make_float2(am[nt][2] + ac[nt][2]*CORR, am[nt][3] + ac[nt][3]*CORR);
    }
}

// ========================= input embedding + MLP =========================
__device__ __forceinline__ float dot96(const float* __restrict__ WTcol,
                                       const float* __restrict__ vin)
{
    float s = 0.f;
    #pragma unroll 8
    for (int k4 = 0; k4 < 24; k4++) {
        float4 a = ((const float4*)vin)[k4];
        s = fmaf(WTcol[(4*k4+0)*96], a.x, s);
        s = fmaf(WTcol[(4*k4+1)*96], a.y, s);
        s = fmaf(WTcol[(4*k4+2)*96], a.z, s);
        s = fmaf(WTcol[(4*k4+3)*96], a.w, s);
    }
    return s;
}

__global__ void __launch_bounds__(768) input_kernel(const int* __restrict__ q,
    const int* __restrict__ rw, const int* __restrict__ cl,
    const float* __restrict__ demb, const float* __restrict__ remb,
    const float* __restrict__ cemb, const float* __restrict__ inb)
{
    extern __shared__ float sm[];
    float* sW0 = sm;
    float* sWT = sm + 48*96;
    float* svb = sWT + 3*9216;
    for (int i = threadIdx.x; i < 48*96;  i += 768) sW0[i] = g_WTin0[i];
    for (int i = threadIdx.x; i < 3*9216; i += 768) sWT[i] = g_WTin[i];
    __syncthreads();

    int slot = threadIdx.x / 96, j = threadIdx.x % 96;
    float* v0 = svb + slot*240;
    float* vA = v0 + 48;
    float* vB = vA + 96;
    int sg = blockIdx.x*8 + slot;
    int stride = gridDim.x*8;
    int iters = (NNODE + stride - 1) / stride;
    float b0 = inb[j], b1 = inb[96+j], b2 = inb[192+j], b3 = inb[288+j];

    for (int it = 0; it < iters; it++) {
        int node = sg + it*stride;
        bool act = node < NNODE;
        int n = act ? node : NNODE-1;
        if (j < 16)      v0[j] = demb[q[n]*16 + j];
        else if (j < 32) v0[j] = remb[rw[n]*16 + (j-16)];
        else if (j < 48) v0[j] = cemb[cl[n]*16 + (j-32)];
        __syncthreads();
        float s = b0;
        #pragma unroll
        for (int k4 = 0; k4 < 12; k4++) {
            float4 a = ((const float4*)v0)[k4];
            s = fmaf(sW0[(4*k4+0)*96+j], a.x, s);
            s = fmaf(sW0[(4*k4+1)*96+j], a.y, s);
            s = fmaf(sW0[(4*k4+2)*96+j], a.z, s);
            s = fmaf(sW0[(4*k4+3)*96+j], a.w, s);
        }
        vA[j] = fmaxf(s, 0.f);
        __syncthreads();
        float t1 = b1 + dot96(sWT + j, vA);
        vB[j] = fmaxf(t1, 0.f);
        __syncthreads();
        float t2 = b2 + dot96(sWT + 9216 + j, vB);
        vA[j] = fmaxf(t2, 0.f);
        __syncthreads();
        float t3 = b3 + dot96(sWT + 2*9216 + j, vA);
        if (act) {
            g_x[(size_t)node*96 + j] = t3;
            __half hh = __float2half_rn(t3);
            g_hH[(size_t)node*104 + j] = hh;
            g_hL[(size_t)node*104 + j] = __float2half_rn((t3 - __half2float(hh))*2048.f);
            g_c[(size_t)node*96 + j] = 0.f;
        }
        __syncthreads();
    }
}

// ========================= fp16 HMMA edge pipeline =========================
// smem (bytes)
#define OFF_B0     0               // 96 f
#define OFF_B1     384
#define OFF_B2     768
#define OFF_NBR    1152            // 6480 -> 7632, pad to 7680
#define OFF_W      7680            // 4 x 96x104 fp16 = 79,872 -> 87,552
#define OFF_AH     87552           // 128x104 fp16 = 26,624
#define OFF_AL     114176          // 26,624
#define OFF_STG    140800          // 128x100 fp32 = 51,200
#define EK_SMEM    192000
#define WIMG       19968           // bytes per W image

#define BAR_PAIR(m) asm volatile("bar.sync %0, %1;" :: "r"(1+(m)), "r"(64) : "memory")

__device__ __forceinline__ void edge_layer(uint32_t aH, uint32_t aL,
                                           uint32_t wH, uint32_t wL,
                                           float (*am)[4], float (*ac)[4])
{
    #pragma unroll
    for (int kt = 0; kt < 6; kt++) {
        uint32_t A0,A1,A2,A3, L0,L1,L2,L3;
        LDSM4(A0,A1,A2,A3, aH + kt*32);
        LDSM4(L0,L1,L2,L3, aL + kt*32);
        #pragma unroll
        for (int ntp = 0; ntp < 3; ntp++) {
            uint32_t h0,h1,h2,h3, l0,l1,l2,l3;
            LDSM4T(h0,h1,h2,h3, wH + kt*3328 + ntp*32);
            LDSM4T(l0,l1,l2,l3, wL + kt*3328 + ntp*32);
            MMAF(am[2*ntp  ], A0,A1,A2,A3, h0,h1);
            MMAF(ac[2*ntp  ], L0,L1,L2,L3, h0,h1);
            MMAF(ac[2*ntp  ], A0,A1,A2,A3, l0,l1);
            MMAF(am[2*ntp+1], A0,A1,A2,A3, h2,h3);
            MMAF(ac[2*ntp+1], L0,L1,L2,L3, h2,h3);
            MMAF(ac[2*ntp+1], A0,A1,A2,A3, l2,l3);
        }
    }
}

__global__ void __launch_bounds__(512) edge_tc_kernel(const float* __restrict__ msgb)
{
    extern __shared__ char smc[];
    uint32_t sbase = smem_u32(smc);
    float* sb0 = (float*)(smc + OFF_B0);
    float* sb1 = (float*)(smc + OFF_B1);
    float* sb2 = (float*)(smc + OFF_B2);
    int*  snbr = (int*)(smc + OFF_NBR);
    float* stg = (float*)(smc + OFF_STG);
    int tid = threadIdx.x, lane = tid & 31, wid = tid >> 5;

    if (tid < 96) { sb0[tid]=msgb[tid]; sb1[tid]=msgb[96+tid]; sb2[tid]=msgb[192+tid]; }
    if (tid < 81) {
        int u = tid;
        int ru = u/9, cu = u%9, bu = (ru/3)*3 + cu/3;
        int cnt = 0;
        for (int v = 0; v < 81; v++) {
            if (v == u) continue;
            int rv = v/9, cv = v%9, bv = (rv/3)*3 + cv/3;
            if (rv == ru || cv == cu || bv == bu) snbr[u*20 + cnt++] = v;
        }
    }
    for (int i = tid; i < 4992; i += 512)
        ((uint4*)(smc + OFF_W))[i] = ((const uint4*)g_Wmsg)[i];
    __syncthreads();

    int mtile = wid >> 1, nhalf = wid & 1;
    uint32_t aH = sbase + OFF_AH + (uint32_t)(((mtile*16 + (lane&15))*104 + ((lane>>4)<<3))*2);
    uint32_t aL = aH + (OFF_AL - OFF_AH);
    uint32_t wfo = (uint32_t)((((lane&15))*104 + nhalf*48 + ((lane>>4)<<3))*2);
    uint32_t w1h = sbase + OFF_W + wfo;
    uint32_t w1l = w1h + WIMG;
    uint32_t w2h = w1h + 2*WIMG;
    uint32_t w2l = w1h + 3*WIMG;
    int cb = (lane & 3) * 2;
    int r0 = mtile*16 + (lane >> 2);
    // build mapping: pair p owns rows [16p,16p+16), thread t=tid&63: row16=t&15, quarter=t>>4
    int t64 = tid & 63;
    int rB = mtile*16 + (t64 & 15);
    int qB = t64 >> 4;
    char* ahc = smc + OFF_AH;
    char* alc = smc + OFF_AL;

    for (int g = blockIdx.x; g < NTILES; g += gridDim.x) {
        // ---- build E0 = relu(a_src + a_dst + b0) -> hi/lo fp16 images (pair-local) ----
        if (rB < 120) {
            int dnode = g*6 + rB/20;
            int cell = dnode % 81;
            int srcn = dnode - cell + snbr[cell*20 + (rB % 20)];
            const float4* aS = (const float4*)(g_S1 + (size_t)srcn*576 + qB*24);
            const float4* aD = (const float4*)(g_S1 + (size_t)dnode*576 + 96 + qB*24);
            const float4* bB = (const float4*)(sb0 + qB*24);
            #pragma unroll
            for (int k4 = 0; k4 < 6; k4++) {
                float4 s = aS[k4], d = aD[k4], b = bB[k4];
                float v0 = fmaxf(s.x+d.x+b.x, 0.f);
                float v1 = fmaxf(s.y+d.y+b.y, 0.f);
                float v2 = fmaxf(s.z+d.z+b.z, 0.f);
                float v3 = fmaxf(s.w+d.w+b.w, 0.f);
                int c = qB*24 + k4*4;
                uint32_t h01 = pk2(v0, v1), h23 = pk2(v2, v3);
                float2 f01 = __half22float2(*(__half2*)&h01);
                float2 f23 = __half22float2(*(__half2*)&h23);
                *(uint32_t*)(ahc + (rB*104 + c)*2)     = h01;
                *(uint32_t*)(ahc + (rB*104 + c + 2)*2) = h23;
                *(uint32_t*)(alc + (rB*104 + c)*2)     = pk2((v0-f01.x)*2048.f, (v1-f01.y)*2048.f);
                *(uint32_t*)(alc + (rB*104 + c + 2)*2) = pk2((v2-f23.x)*2048.f, (v3-f23.y)*2048.f);
            }
        } else {
            #pragma unroll
            for (int k4 = 0; k4 < 6; k4++) {
                int c = qB*24 + k4*4;
                *(uint32_t*)(ahc + (rB*104 + c)*2)     = 0u;
                *(uint32_t*)(ahc + (rB*104 + c + 2)*2) = 0u;
                *(uint32_t*)(alc + (rB*104 + c)*2)     = 0u;
                *(uint32_t*)(alc + (rB*104 + c + 2)*2) = 0u;
            }
        }
        BAR_PAIR(mtile);

        // ---- layer 1 ----
        float am[6][4], ac[6][4];
        #pragma unroll
        for (int nt = 0; nt < 6; nt++) {
            int c = nhalf*48 + nt*8 + cb;
            am[nt][0]=sb1[c]; am[nt][1]=sb1[c+1]; am[nt][2]=sb1[c]; am[nt][3]=sb1[c+1];
            ac[nt][0]=0.f; ac[nt][1]=0.f; ac[nt][2]=0.f; ac[nt][3]=0.f;
        }
        edge_layer(aH, aL, w1h, w1l, am, ac);
        BAR_PAIR(mtile);   // both pair warps done reading A
        // epilogue 1: relu -> hi/lo back into A images (own rows)
        #pragma unroll
        for (int nt = 0; nt < 6; nt++) {
            int c = nhalf*48 + nt*8 + cb;
            float v0 = fmaxf(am[nt][0] + ac[nt][0]*CORR, 0.f);
            float v1 = fmaxf(am[nt][1] + ac[nt][1]*CORR, 0.f);
            float v2 = fmaxf(am[nt][2] + ac[nt][2]*CORR, 0.f);
            float v3 = fmaxf(am[nt][3] + ac[nt][3]*CORR, 0.f);
            uint32_t h01 = pk2(v0, v1), h23 = pk2(v2, v3);
            float2 f01 = __half22float2(*(__half2*)&h01);
            float2 f23 = __half22float2(*(__half2*)&h23);
            *(uint32_t*)(ahc + (r0*104 + c)*2)     = h01;
            *(uint32_t*)(ahc + ((r0+8)*104 + c)*2) = h23;
            *(uint32_t*)(alc + (r0*104 + c)*2)     = pk2((v0-f01.x)*2048.f, (v1-f01.y)*2048.f);
            *(uint32_t*)(alc + ((r0+8)*104 + c)*2) = pk2((v2-f23.x)*2048.f, (v3-f23.y)*2048.f);
        }
        BAR_PAIR(mtile);

        // ---- layer 2 ----
        #pragma unroll
        for (int nt = 0; nt < 6; nt++) {
            int c = nhalf*48 + nt*8 + cb;
            am[nt][0]=sb2[c]; am[nt][1]=sb2[c+1]; am[nt][2]=sb2[c]; am[nt][3]=sb2[c+1];
            ac[nt][0]=0.f; ac[nt][1]=0.f; ac[nt][2]=0.f; ac[nt][3]=0.f;
        }
        edge_layer(aH, aL, w2h, w2l, am, ac);
        // epilogue 2: relu -> fp32 stage (separate region, own rows)
        #pragma unroll
        for (int nt = 0; nt < 6; nt++) {
            int c = nhalf*48 + nt*8 + cb;
            stg[r0*100 + c]       = fmaxf(am[nt][0] + ac[nt][0]*CORR, 0.f);
            stg[r0*100 + c + 1]   = fmaxf(am[nt][1] + ac[nt][1]*CORR, 0.f);
            stg[(r0+8)*100 + c]   = fmaxf(am[nt][2] + ac[nt][2]*CORR, 0.f);
            stg[(r0+8)*100 + c+1] = fmaxf(am[nt][3] + ac[nt][3]*CORR, 0.f);
        }
        __syncthreads();
        // per-node sum -> Z hi/lo images
        for (int idx = tid; idx < 576; idx += 512) {
            int i = idx / 96, c = idx % 96;
            float s = 0.f;
            #pragma unroll
            for (int e = 0; e < 20; e++) s += stg[(i*20+e)*100 + c];
            __half hh = __float2half_rn(s);
            size_t o = (size_t)(g*6+i)*104 + c;
            g_ZH[o] = hh;
            g_ZL[o] = __float2half_rn((s - __half2float(hh))*2048.f);
        }
        __syncthreads();
    }
}

// ========================= LSTM pointwise + per-step logits =========================
__global__ void __launch_bounds__(768) lstm_kernel(const float* __restrict__ outW,
                                                   const float* __restrict__ outb, int t)
{
    int slot = threadIdx.x / 96, j = threadIdx.x % 96;
    int n = blockIdx.x*8 + slot;
    __shared__ float sh[8][HD];
    size_t b4 = (size_t)n*384 + j;
    float gi = g_gx[b4      ] + g_gm[b4      ] + g_bc[j];
    float gf = g_gx[b4 +  96] + g_gm[b4 +  96] + g_bc[96+j];
    float gg = g_gx[b4 + 192] + g_gm[b4 + 192] + g_bc[192+j];
    float go = g_gx[b4 + 288] + g_gm[b4 + 288] + g_bc[288+j];
    if (t > 0) {
        const float* hw = g_S1 + (size_t)n*576 + 192 + j;
        gi += hw[0]; gf += hw[96]; gg += hw[192]; go += hw[288];
    }
    float si = 1.f/(1.f + expf(-gi));
    float sf = 1.f/(1.f + expf(-gf));
    float so = 1.f/(1.f + expf(-go));
    float cn = sf * g_c[(size_t)n*96 + j] + si * tanhf(gg);
    float hn = so * tanhf(cn);
    g_c[(size_t)n*96 + j] = cn;
    __half hh = __float2half_rn(hn);
    g_hH[(size_t)n*104 + j] = hh;
    g_hL[(size_t)n*104 + j] = __float2half_rn((hn - __half2float(hh))*2048.f);
    sh[slot][j] = hn;
    __syncthreads();
    if (j < 10) {
        float s = outb[j];
        const float* w = outW + j*96;
        #pragma unroll 8
        for (int k = 0; k < 96; k++) s = fmaf(sh[slot][k], w[k], s);
        g_logits[((size_t)t*NNODE + n)*10 + j] = s;
    }
}

// ========================= preds / loss / lf =========================
__global__ void finalize_kernel(const int* __restrict__ labels,
                                float* __restrict__ out, int out_size)
{
    int idx = blockIdx.x*blockDim.x + threadIdx.x;
    double term = 0.0;
    if (idx < TSTEPS*NNODE) {
        const float* l = g_logits + (size_t)idx*10;
        float mx = l[0]; int am = 0;
        #pragma unroll
        for (int d = 1; d < 10; d++) if (l[d] > mx) { mx = l[d]; am = d; }
        float se = 0.f;
        #pragma unroll
        for (int d = 0; d < 10; d++) se += expf(l[d] - mx);
        float lse = mx + logf(se);
        int lab = labels[idx % NNODE];
        term = (double)(lse - l[lab]);

        const int FULL = TSTEPS*NNODE*11 + 1;
        if (out_size >= FULL) {
            out[idx] = (float)am;
            float* lf = out + TSTEPS*NNODE + 1 + (size_t)idx*10;
            #pragma unroll
            for (int d = 0; d < 10; d++) lf[d] = l[d];
        } else {
            float* lf = out + (size_t)idx*10;
            #pragma unroll
            for (int d = 0; d < 10; d++) lf[d] = l[d];
        }
    }
    #pragma unroll
    for (int o = 16; o; o >>= 1)
        term += __shfl_down_sync(0xffffffffu, term, o);
    if ((threadIdx.x & 31) == 0 && term != 0.0) atomicAdd(&g_loss, term);
}

__global__ void loss_kernel(float* __restrict__ out, int out_size)
{
    const int FULL = TSTEPS*NNODE*11 + 1;
    if (out_size >= FULL)
        out[TSTEPS*NNODE] = (float)(g_loss / (double)(TSTEPS*NNODE));
}

// ========================= launch =========================
extern "C" void kernel_launch(void* const* d_in, const int* in_sizes, int n_in,
                              void* d_out, int out_size)
{
    const int*   q      = (const int*)  d_in[0];
    const int*   row    = (const int*)  d_in[1];
    const int*   col    = (const int*)  d_in[2];
    const int*   labels = (const int*)  d_in[3];
    const float* d_emb  = (const float*)d_in[6];
    const float* r_emb  = (const float*)d_in[7];
    const float* c_emb  = (const float*)d_in[8];
    const float* in_W0  = (const float*)d_in[9];
    const float* in_W   = (const float*)d_in[10];
    const float* in_b   = (const float*)d_in[11];
    const float* msg_W0 = (const float*)d_in[12];
    const float* msg_W  = (const float*)d_in[13];
    const float* msg_b  = (const float*)d_in[14];
    const float* W_ih   = (const float*)d_in[15];
    const float* W_hh   = (const float*)d_in[16];
    const float* out_W  = (const float*)d_in[17];
    const float* out_b  = (const float*)d_in[18];
    float* out = (float*)d_out;

    const int IN_SMEM = (48*96 + 3*9216 + 8*240) * 4;
    cudaFuncSetAttribute(input_kernel,   cudaFuncAttributeMaxDynamicSharedMemorySize, IN_SMEM);
    cudaFuncSetAttribute(edge_tc_kernel, cudaFuncAttributeMaxDynamicSharedMemorySize, EK_SMEM);
    cudaFuncSetAttribute(gemm_f16,       cudaFuncAttributeMaxDynamicSharedMemorySize, GEMM_SMEM);

    float *px, *pS1, *pgx, *pgm;
    __half *phH, *phL, *pZH, *pZL, *pWpH, *pWpL, *pWcH, *pWcL;
    cudaGetSymbolAddress((void**)&px,   g_x);
    cudaGetSymbolAddress((void**)&pS1,  g_S1);
    cudaGetSymbolAddress((void**)&pgx,  g_gx);
    cudaGetSymbolAddress((void**)&pgm,  g_gm);
    cudaGetSymbolAddress((void**)&phH,  g_hH);
    cudaGetSymbolAddress((void**)&phL,  g_hL);
    cudaGetSymbolAddress((void**)&pZH,  g_ZH);
    cudaGetSymbolAddress((void**)&pZL,  g_ZL);
    cudaGetSymbolAddress((void**)&pWpH, g_WpackTH);
    cudaGetSymbolAddress((void**)&pWpL, g_WpackTL);
    cudaGetSymbolAddress((void**)&pWcH, g_WcombTH);
    cudaGetSymbolAddress((void**)&pWcL, g_WcombTL);

    pack_kernel<<<192, 256>>>(msg_W, in_W, in_W0, msg_W0, W_hh, W_ih, msg_b);
    input_kernel<<<152, 768, IN_SMEM>>>(q, row, col, d_emb, r_emb, c_emb, in_b);
    // gx = x @ W_ih[:, :96]^T  (step-invariant, once)
    sgemm_awt<<<dim3(384/64, NNODE/64), 256>>>(px, W_ih, pgx, 384, 192, 0);

    for (int t = 0; t < TSTEPS; t++) {
        // S1 = h @ [W0a; W0b; W_hh]^T
        gemm_f16<<<dim3(9, NNODE/64), 256, GEMM_SMEM>>>(phH, phL, pWpH, pWpL, pS1, 576);
        edge_tc_kernel<<<152, 512, EK_SMEM>>>(msg_b);
        // gm = Z @ Wcomb^T
        gemm_f16<<<dim3(6, NNODE/64), 256, GEMM_SMEM>>>(pZH, pZL, pWcH, pWcL, pgm, 384);
        lstm_kernel<<<NNODE/8, 768>>>(out_W, out_b, t);
    }

    finalize_kernel<<<(TSTEPS*NNODE + 255)/256, 256>>>(labels, out, out_size);
    loss_kernel<<<1, 1>>>(out, out_size);
}